// round 1
// baseline (speedup 1.0000x reference)
#include <cuda_runtime.h>
#include <cuda_bf16.h>
#include <math.h>

#define NN 48758
#define DD 128
#define RR 4
#define EMAX 780000

// ---------------- device scratch (static, no runtime alloc) ----------------
__device__ __align__(16) float g_h[(size_t)NN * DD];      // hidden state
__device__ __align__(16) float g_xw[(size_t)NN * DD];     // win-transformed
__device__ __align__(16) float g_y[(size_t)NN * DD * RR]; // wrel-transformed, layout [node][rel][c]
__device__ __align__(16) float g_z[(size_t)NN * DD];      // layer message output
__device__ int   g_off[NN + 1];
__device__ int   g_cur[NN];
__device__ int   g_degsrc[NN];
__device__ int   g_degdst[NN];
__device__ int   g_srcs[EMAX];
__device__ int   g_types[EMAX];
__device__ float g_norms[EMAX];
__device__ float g_colsum[DD];
__device__ float g_colsq[DD];

// ---------------- small helpers ----------------
__device__ __forceinline__ float dinvf(int dg) {
    return dg > 0 ? rsqrtf((float)dg) : 0.0f;
}

// ---------------- CSR build ----------------
__global__ void zero_kernel() {
    int i = blockIdx.x * blockDim.x + threadIdx.x;
    if (i < NN) { g_degsrc[i] = 0; g_degdst[i] = 0; }
    if (i < DD) { g_colsum[i] = 0.0f; g_colsq[i] = 0.0f; }
}

__global__ void hist_kernel(const int* __restrict__ ei, int E) {
    int e = blockIdx.x * blockDim.x + threadIdx.x;
    if (e >= E) return;
    atomicAdd(&g_degdst[ei[e]], 1);       // dst = edge_index[0]
    atomicAdd(&g_degsrc[ei[E + e]], 1);   // src = edge_index[1]
}

__global__ void scan_kernel(int E) {
    __shared__ int sm[1024];
    __shared__ int carry_s;
    int tid = threadIdx.x;
    if (tid == 0) carry_s = 0;
    __syncthreads();
    for (int base = 0; base < NN; base += 1024) {
        int i = base + tid;
        int v = (i < NN) ? g_degdst[i] : 0;
        sm[tid] = v;
        __syncthreads();
        for (int ofs = 1; ofs < 1024; ofs <<= 1) {
            int t = 0;
            if (tid >= ofs) t = sm[tid - ofs];
            __syncthreads();
            if (tid >= ofs) sm[tid] += t;
            __syncthreads();
        }
        int incl = sm[tid];
        int carry = carry_s;
        if (i < NN) {
            int exv = carry + incl - v;
            g_off[i] = exv;
            g_cur[i] = exv;
        }
        __syncthreads();
        if (tid == 1023) carry_s = carry + incl;
        __syncthreads();
    }
    if (tid == 0) g_off[NN] = E;
}

__global__ void scatter_kernel(const int* __restrict__ ei, const int* __restrict__ et, int E) {
    int e = blockIdx.x * blockDim.x + threadIdx.x;
    if (e >= E) return;
    int d = ei[e];
    int s = ei[E + e];
    int slot = atomicAdd(&g_cur[d], 1);
    g_srcs[slot] = s;
    g_types[slot] = et[e];
    g_norms[slot] = dinvf(g_degsrc[d]) * dinvf(g_degsrc[s]);
}

// ---------------- SGEMM: C[M x Nn] = A[M x 128] @ B + bias ----------------
// relmode==0: B is row-major [128 x Nn]
// relmode==1: B is wrel layout [R][128][128]; logical col n' -> r=n'>>7, nn=n'&127
#define BM 64
#define BN 64
#define BK 16

__global__ void sgemm_kernel(const float* __restrict__ A, const float* __restrict__ B,
                             const float* __restrict__ bias, float* __restrict__ C,
                             int M, int Nn, int relmode) {
    __shared__ __align__(16) float Ast[BK][BM];
    __shared__ __align__(16) float Bs[BK][BN];
    int tid = threadIdx.x;          // 256 threads
    int bm = blockIdx.y * BM;
    int bn = blockIdx.x * BN;
    int tx = tid & 15;
    int ty = tid >> 4;
    float acc[4][4];
#pragma unroll
    for (int i = 0; i < 4; i++)
#pragma unroll
        for (int j = 0; j < 4; j++) acc[i][j] = 0.0f;

    int lam = tid >> 2;             // 0..63
    int lak = (tid & 3) * 4;        // 0,4,8,12
    int lbk = tid >> 4;             // 0..15
    int lbn = (tid & 15) * 4;       // 0..60

    for (int k0 = 0; k0 < 128; k0 += BK) {
        // A tile (with M guard)
        int arow = bm + lam;
        float4 a4 = make_float4(0.f, 0.f, 0.f, 0.f);
        if (arow < M) a4 = *(const float4*)(A + (size_t)arow * 128 + k0 + lak);
        Ast[lak + 0][lam] = a4.x;
        Ast[lak + 1][lam] = a4.y;
        Ast[lak + 2][lam] = a4.z;
        Ast[lak + 3][lam] = a4.w;
        // B tile
        int bk = k0 + lbk;
        int n0 = bn + lbn;
        float4 b4;
        if (relmode) {
            int r = n0 >> 7;
            int nn = n0 & 127;
            b4 = *(const float4*)(B + (((size_t)(r << 7) + bk) << 7) + nn);
        } else {
            b4 = *(const float4*)(B + (size_t)bk * Nn + n0);
        }
        *(float4*)&Bs[lbk][lbn] = b4;
        __syncthreads();
#pragma unroll
        for (int k = 0; k < BK; k++) {
            float4 a = *(float4*)&Ast[k][ty * 4];
            float4 b = *(float4*)&Bs[k][tx * 4];
            acc[0][0] += a.x * b.x; acc[0][1] += a.x * b.y; acc[0][2] += a.x * b.z; acc[0][3] += a.x * b.w;
            acc[1][0] += a.y * b.x; acc[1][1] += a.y * b.y; acc[1][2] += a.y * b.z; acc[1][3] += a.y * b.w;
            acc[2][0] += a.z * b.x; acc[2][1] += a.z * b.y; acc[2][2] += a.z * b.z; acc[2][3] += a.z * b.w;
            acc[3][0] += a.w * b.x; acc[3][1] += a.w * b.y; acc[3][2] += a.w * b.z; acc[3][3] += a.w * b.w;
        }
        __syncthreads();
    }
    int ncol = bn + tx * 4;
    float4 bb = make_float4(0.f, 0.f, 0.f, 0.f);
    if (bias) bb = *(const float4*)(bias + ncol);
#pragma unroll
    for (int i = 0; i < 4; i++) {
        int row = bm + ty * 4 + i;
        if (row < M) {
            float4 o;
            o.x = acc[i][0] + bb.x;
            o.y = acc[i][1] + bb.y;
            o.z = acc[i][2] + bb.z;
            o.w = acc[i][3] + bb.w;
            *(float4*)(C + (size_t)row * Nn + ncol) = o;
        }
    }
}

// ---------------- BatchNorm stats + apply + relu ----------------
__global__ void colstats_kernel() {
    int c = threadIdx.x;   // 128 threads
    float s = 0.f, q = 0.f;
    for (int r = blockIdx.x; r < NN; r += gridDim.x) {
        float v = g_h[(size_t)r * DD + c];
        s += v;
        q += v * v;
    }
    atomicAdd(&g_colsum[c], s);
    atomicAdd(&g_colsq[c], q);
}

__global__ void bnrelu_kernel(const float* __restrict__ bg, const float* __restrict__ bb) {
    int i = blockIdx.x * blockDim.x + threadIdx.x;
    if (i >= NN * DD) return;
    int c = i & 127;
    float invn = 1.0f / (float)NN;
    float mu = g_colsum[c] * invn;
    float var = g_colsq[c] * invn - mu * mu;
    float v = (g_h[i] - mu) * rsqrtf(var + 1e-5f) * bg[c] + bb[c];
    g_h[i] = v > 0.f ? v : 0.f;
}

// ---------------- edge stage: one warp per dst node ----------------
// y layout: [node][rel][c] -> g_y[s*512 + t*128 + c]
__global__ void edge_kernel() {
    int w = (blockIdx.x * blockDim.x + threadIdx.x) >> 5;
    if (w >= NN) return;
    int lane = threadIdx.x & 31;
    int c = lane << 2;
    int s0 = g_off[w], s1 = g_off[w + 1];
    float4 zo;
    if (s0 == s1) {
        zo = make_float4(0.f, 0.f, 0.f, 0.f);
    } else {
        float mx = -1e30f, my = -1e30f, mz = -1e30f, mw = -1e30f;
        for (int e = s0; e < s1; e++) {
            int s = g_srcs[e];
            int t = g_types[e];
            float4 r = *(const float4*)&g_y[((size_t)s << 9) + (t << 7) + c];
            mx = fmaxf(mx, r.x); my = fmaxf(my, r.y);
            mz = fmaxf(mz, r.z); mw = fmaxf(mw, r.w);
        }
        float dx = 0.f, dy = 0.f, dz = 0.f, dw = 0.f;
        float nx = 0.f, ny = 0.f, nz = 0.f, nw = 0.f;
        float gx = 0.f, gy = 0.f, gz = 0.f, gw = 0.f;
        for (int e = s0; e < s1; e++) {
            int s = g_srcs[e];
            int t = g_types[e];
            float wn = g_norms[e];
            float4 r = *(const float4*)&g_y[((size_t)s << 9) + (t << 7) + c];
            float ex = __expf(r.x - mx); dx += ex; nx += r.x * ex;
            float ey = __expf(r.y - my); dy += ey; ny += r.y * ey;
            float ez = __expf(r.z - mz); dz += ez; nz += r.z * ez;
            float ew = __expf(r.w - mw); dw += ew; nw += r.w * ew;
            float4 xj = *(const float4*)&g_xw[((size_t)s << 7) + c];
            gx += xj.x * wn; gy += xj.y * wn; gz += xj.z * wn; gw += xj.w * wn;
        }
        float m0 = nx / dx, m1 = ny / dy, m2 = nz / dz, m3 = nw / dw;
        zo.x = gx + 0.1f * fmaxf(m0, 0.f);
        zo.y = gy + 0.1f * fmaxf(m1, 0.f);
        zo.z = gz + 0.1f * fmaxf(m2, 0.f);
        zo.w = gw + 0.1f * fmaxf(m3, 0.f);
    }
    *(float4*)&g_z[((size_t)w << 7) + c] = zo;
}

// ---------------- final: exact gelu + gather at idx ----------------
__global__ void gelu_gather_kernel(const int* __restrict__ idx, float* __restrict__ out, int ni) {
    int i = blockIdx.x * blockDim.x + threadIdx.x;
    if (i >= ni * DD) return;
    int row = idx[i >> 7];
    float v = g_h[((size_t)row << 7) + (i & 127)];
    out[i] = 0.5f * v * (1.0f + erff(v * 0.70710678118654752f));
}

// ---------------- host launcher ----------------
static void* sym_addr(const void* sym) {
    void* p = nullptr;
    cudaGetSymbolAddress(&p, sym);
    return p;
}

extern "C" void kernel_launch(void* const* d_in, const int* in_sizes, int n_in,
                              void* d_out, int out_size) {
    // resolve input ordering: dict order (from setup_inputs) vs reference-signature order
    int ix, iei, iidx, iet, ipw, ipb, ibg, ibb, iww, iwb, iwr, iow, iob;
    if (in_sizes[1] > 1000000) {
        // dict order: x, edge_index, idx, edge_type, edge_weight, proj_w, proj_b,
        //             bn_g, bn_b, win_w, win_b, wrel, out_w, out_b
        ix = 0; iei = 1; iidx = 2; iet = 3; ipw = 5; ipb = 6; ibg = 7; ibb = 8;
        iww = 9; iwb = 10; iwr = 11; iow = 12; iob = 13;
    } else {
        // signature order: x, edge_weight, proj_w, proj_b, bn_g, bn_b, win_w, win_b,
        //                  wrel, out_w, out_b, edge_index, edge_type, idx
        ix = 0; ipw = 2; ipb = 3; ibg = 4; ibb = 5; iww = 6; iwb = 7;
        iwr = 8; iow = 9; iob = 10; iei = 11; iet = 12; iidx = 13;
    }

    const float* x   = (const float*)d_in[ix];
    const int*   ei  = (const int*)d_in[iei];
    const int*   et  = (const int*)d_in[iet];
    const int*   idx = (const int*)d_in[iidx];
    const float* pw  = (const float*)d_in[ipw];
    const float* pb  = (const float*)d_in[ipb];
    const float* bg  = (const float*)d_in[ibg];
    const float* bb  = (const float*)d_in[ibb];
    const float* ww  = (const float*)d_in[iww];
    const float* wb  = (const float*)d_in[iwb];
    const float* wr  = (const float*)d_in[iwr];
    const float* ow  = (const float*)d_in[iow];
    const float* ob  = (const float*)d_in[iob];

    int E  = in_sizes[iei] / 2;
    int NI = out_size / DD;

    float* hbuf  = (float*)sym_addr(g_h);
    float* xwbuf = (float*)sym_addr(g_xw);
    float* ybuf  = (float*)sym_addr(g_y);
    float* zbuf  = (float*)sym_addr(g_z);

    // CSR build
    zero_kernel<<<(NN + 255) / 256, 256>>>();
    hist_kernel<<<(E + 255) / 256, 256>>>(ei, E);
    scan_kernel<<<1, 1024>>>(E);
    scatter_kernel<<<(E + 255) / 256, 256>>>(ei, et, E);

    dim3 gemm_blk(256);
    dim3 g128(DD / BN, (NN + BM - 1) / BM);   // (2, 762)
    dim3 g512(512 / BN, (NN + BM - 1) / BM);  // (8, 762)

    // projection + batchnorm + relu
    sgemm_kernel<<<g128, gemm_blk>>>(x, pw, pb, hbuf, NN, DD, 0);
    colstats_kernel<<<512, 128>>>();
    bnrelu_kernel<<<(NN * DD + 255) / 256, 256>>>(bg, bb);

    // two DAN layers
    for (int l = 0; l < 2; l++) {
        const float* lww = ww + (size_t)l * DD * DD;
        const float* lwb = wb + (size_t)l * DD;
        const float* lwr = wr + (size_t)l * RR * DD * DD;
        const float* low = ow + (size_t)l * DD * DD;
        const float* lob = ob + (size_t)l * DD;

        // xw = h @ win + b
        sgemm_kernel<<<g128, gemm_blk>>>(hbuf, lww, lwb, xwbuf, NN, DD, 0);
        // y[:, r*128:(r+1)*128] = xw @ wrel[r]   (fused, N'=512)
        sgemm_kernel<<<g512, gemm_blk>>>(xwbuf, lwr, nullptr, ybuf, NN, 512, 1);
        // edge aggregation: msg_gcn + 0.1*relu(softmax-weighted msg)
        edge_kernel<<<(NN * 32 + 255) / 256, 256>>>();
        // h = z @ out_w + out_b
        sgemm_kernel<<<g128, gemm_blk>>>(zbuf, low, lob, hbuf, NN, DD, 0);
    }

    // gelu(exact) + gather
    gelu_gather_kernel<<<(NI * DD + 255) / 256, 256>>>(idx, (float*)d_out, NI);
}

// round 2
// speedup vs baseline: 1.3894x; 1.3894x over previous
#include <cuda_runtime.h>
#include <cuda_bf16.h>
#include <math.h>

#define NN 48758
#define DD 128
#define RR 4
#define EMAX 780000

// ---------------- device scratch (static, no runtime alloc) ----------------
__device__ __align__(16) float g_h[(size_t)NN * DD];        // hidden state
__device__ __align__(16) float g_hy[(size_t)NN * 640];      // [node][ xw(128) | y_r0..3 (512) ]
__device__ __align__(16) float g_z[(size_t)NN * DD];        // layer message output
__device__ __align__(16) float g_wc[2 * 128 * 640];         // combined weights per layer [k][640]
__device__ __align__(16) float g_bc[2 * 640];               // combined bias per layer
__device__ int   g_off[NN + 1];
__device__ int   g_cur[NN];
__device__ int   g_degsrc[NN];
__device__ int   g_degdst[NN];
__device__ int   g_srcs[EMAX];
__device__ int   g_types[EMAX];
__device__ float g_norms[EMAX];
__device__ float g_colsum[DD];
__device__ float g_colsq[DD];

__device__ __forceinline__ float dinvf(int dg) {
    return dg > 0 ? rsqrtf((float)dg) : 0.0f;
}

// ---------------- CSR build ----------------
__global__ void zero_kernel() {
    int i = blockIdx.x * blockDim.x + threadIdx.x;
    if (i < NN) { g_degsrc[i] = 0; g_degdst[i] = 0; }
    if (i < DD) { g_colsum[i] = 0.0f; g_colsq[i] = 0.0f; }
}

__global__ void hist_kernel(const int* __restrict__ ei, int E) {
    int e = blockIdx.x * blockDim.x + threadIdx.x;
    if (e >= E) return;
    atomicAdd(&g_degdst[ei[e]], 1);       // dst = edge_index[0]
    atomicAdd(&g_degsrc[ei[E + e]], 1);   // src = edge_index[1]
}

__global__ void scan_kernel(int E) {
    __shared__ int sm[1024];
    __shared__ int carry_s;
    int tid = threadIdx.x;
    if (tid == 0) carry_s = 0;
    __syncthreads();
    for (int base = 0; base < NN; base += 1024) {
        int i = base + tid;
        int v = (i < NN) ? g_degdst[i] : 0;
        sm[tid] = v;
        __syncthreads();
        for (int ofs = 1; ofs < 1024; ofs <<= 1) {
            int t = 0;
            if (tid >= ofs) t = sm[tid - ofs];
            __syncthreads();
            if (tid >= ofs) sm[tid] += t;
            __syncthreads();
        }
        int incl = sm[tid];
        int carry = carry_s;
        if (i < NN) {
            int exv = carry + incl - v;
            g_off[i] = exv;
            g_cur[i] = exv;
        }
        __syncthreads();
        if (tid == 1023) carry_s = carry + incl;
        __syncthreads();
    }
    if (tid == 0) g_off[NN] = E;
}

__global__ void scatter_kernel(const int* __restrict__ ei, const int* __restrict__ et, int E) {
    int e = blockIdx.x * blockDim.x + threadIdx.x;
    if (e >= E) return;
    int d = ei[e];
    int s = ei[E + e];
    int slot = atomicAdd(&g_cur[d], 1);
    g_srcs[slot] = s;
    g_types[slot] = et[e];
    g_norms[slot] = dinvf(g_degsrc[d]) * dinvf(g_degsrc[s]);
}

// ---------------- weight prep: combined weights + bias ----------------
// Wc[l] layout [128 k][640 n]: cols 0..127 = win[l]; cols 128+r*128+nn = (win@wrel_r)[k][nn]
__global__ void wc_kernel(const float* __restrict__ ww, const float* __restrict__ wr) {
    __shared__ float wrs[32][128];
    int combo = blockIdx.x;         // l*4 + r
    int l = combo >> 2, r = combo & 3;
    int k0 = blockIdx.y * 32;
    const float* win  = ww + (size_t)l * 16384;
    const float* wrel = wr + (size_t)(l * 4 + r) * 16384;
    int tid = threadIdx.x;
    int kl = tid >> 3;              // 0..31
    int n0 = (tid & 7) << 4;        // 0..112
    float acc[16];
#pragma unroll
    for (int i = 0; i < 16; i++) acc[i] = 0.0f;
    for (int jb = 0; jb < 128; jb += 32) {
        __syncthreads();
#pragma unroll
        for (int i = 0; i < 4; i++) {
            int linear = tid + 256 * i;     // 1024 float4
            int row = linear >> 5;
            int c4 = linear & 31;
            *(float4*)&wrs[row][c4 * 4] = *(const float4*)(wrel + (size_t)(jb + row) * 128 + c4 * 4);
        }
        __syncthreads();
        for (int j = 0; j < 32; j++) {
            float wv = win[(size_t)(k0 + kl) * 128 + jb + j];
#pragma unroll
            for (int i4 = 0; i4 < 4; i4++) {
                float4 v = *(float4*)&wrs[j][n0 + i4 * 4];
                acc[i4 * 4 + 0] += wv * v.x;
                acc[i4 * 4 + 1] += wv * v.y;
                acc[i4 * 4 + 2] += wv * v.z;
                acc[i4 * 4 + 3] += wv * v.w;
            }
        }
    }
    float* out = g_wc + (size_t)l * 81920 + (size_t)(k0 + kl) * 640 + 128 + (r << 7) + n0;
#pragma unroll
    for (int i4 = 0; i4 < 4; i4++)
        *(float4*)(out + i4 * 4) = make_float4(acc[i4 * 4], acc[i4 * 4 + 1], acc[i4 * 4 + 2], acc[i4 * 4 + 3]);
}

__global__ void prep_kernel(const float* __restrict__ ww, const float* __restrict__ wbv,
                            const float* __restrict__ wr) {
    int i = blockIdx.x * blockDim.x + threadIdx.x;
    if (i < 32768) {    // copy win into cols 0..127
        int l = i >> 14, k = (i >> 7) & 127, n = i & 127;
        g_wc[(size_t)l * 81920 + k * 640 + n] = ww[i];
    }
    int j = i - 32768;
    if (j >= 0 && j < 1280) {   // combined bias
        int l = j / 640, n = j % 640;
        if (n < 128) {
            g_bc[l * 640 + n] = wbv[l * 128 + n];
        } else {
            int r = (n - 128) >> 7, nn = (n - 128) & 127;
            const float* wb_ = wbv + l * 128;
            const float* wrel = wr + (size_t)(l * 4 + r) * 16384;
            float s = 0.0f;
            for (int q = 0; q < 128; q++) s += wb_[q] * wrel[q * 128 + nn];
            g_bc[l * 640 + n] = s;
        }
    }
}

// ---------------- tensor-core GEMM: split-bf16 3xMMA (fp32-accurate) ----------------
// C[M x N] = A[M x 128] @ B[128 x N] + bias ; BM=BN=128, BK=32, 256 threads
#define LDSM_X4(R, p) asm volatile( \
    "ldmatrix.sync.aligned.m8n8.x4.shared.b16 {%0,%1,%2,%3}, [%4];" \
    : "=r"((R)[0]), "=r"((R)[1]), "=r"((R)[2]), "=r"((R)[3]) : "r"(p))
#define LDSM_X2T(R, p) asm volatile( \
    "ldmatrix.sync.aligned.m8n8.x2.trans.shared.b16 {%0,%1}, [%2];" \
    : "=r"((R)[0]), "=r"((R)[1]) : "r"(p))
#define MMA_BF16(d, a, b) asm volatile( \
    "mma.sync.aligned.m16n8k16.row.col.f32.bf16.bf16.f32 " \
    "{%0,%1,%2,%3},{%4,%5,%6,%7},{%8,%9},{%0,%1,%2,%3};" \
    : "+f"((d)[0]), "+f"((d)[1]), "+f"((d)[2]), "+f"((d)[3]) \
    : "r"((a)[0]), "r"((a)[1]), "r"((a)[2]), "r"((a)[3]), "r"((b)[0]), "r"((b)[1]))

__device__ __forceinline__ void split_store(__nv_bfloat16* ph, __nv_bfloat16* pl, float2 v) {
    __nv_bfloat16 hx = __float2bfloat16_rn(v.x);
    __nv_bfloat16 hy = __float2bfloat16_rn(v.y);
    __nv_bfloat16 lx = __float2bfloat16_rn(v.x - __bfloat162float(hx));
    __nv_bfloat16 ly = __float2bfloat16_rn(v.y - __bfloat162float(hy));
    *reinterpret_cast<__nv_bfloat162*>(ph) = __halves2bfloat162(hx, hy);
    *reinterpret_cast<__nv_bfloat162*>(pl) = __halves2bfloat162(lx, ly);
}

__global__ __launch_bounds__(256, 2)
void gemm_split_kernel(const float* __restrict__ A, const float* __restrict__ B,
                       const float* __restrict__ bias, float* __restrict__ C,
                       int M, int ldb, int ldc) {
    __shared__ __align__(16) __nv_bfloat16 Ah[128][40];
    __shared__ __align__(16) __nv_bfloat16 Al[128][40];
    __shared__ __align__(16) __nv_bfloat16 Bh[32][136];
    __shared__ __align__(16) __nv_bfloat16 Bl[32][136];

    int tid = threadIdx.x;
    int lane = tid & 31;
    int warp = tid >> 5;
    int wm = warp >> 2;             // 0..1
    int wn = warp & 3;              // 0..3
    int bm = blockIdx.y * 128;
    int bn = blockIdx.x * 128;

    float acc[4][4][4];
#pragma unroll
    for (int a = 0; a < 4; a++)
#pragma unroll
        for (int b = 0; b < 4; b++)
#pragma unroll
            for (int c = 0; c < 4; c++) acc[a][b][c] = 0.0f;

    int la_row = tid >> 3;          // 0..31
    int la_c4 = tid & 7;            // col group (4 floats)

    for (int k0 = 0; k0 < 128; k0 += 32) {
        // A tile 128x32 (fp32 -> split bf16)
#pragma unroll
        for (int i = 0; i < 4; i++) {
            int row = la_row + i * 32;
            int grow = bm + row;
            float4 a4 = make_float4(0.f, 0.f, 0.f, 0.f);
            if (grow < M) a4 = *(const float4*)(A + (size_t)grow * 128 + k0 + la_c4 * 4);
            int c = la_c4 * 4;
            split_store(&Ah[row][c], &Al[row][c], make_float2(a4.x, a4.y));
            split_store(&Ah[row][c + 2], &Al[row][c + 2], make_float2(a4.z, a4.w));
        }
        // B tile 32x128
#pragma unroll
        for (int i = 0; i < 4; i++) {
            int linear = tid + 256 * i;
            int row = linear >> 5;
            int c4 = linear & 31;
            float4 b4 = *(const float4*)(B + (size_t)(k0 + row) * ldb + bn + c4 * 4);
            int c = c4 * 4;
            split_store(&Bh[row][c], &Bl[row][c], make_float2(b4.x, b4.y));
            split_store(&Bh[row][c + 2], &Bl[row][c + 2], make_float2(b4.z, b4.w));
        }
        __syncthreads();

#pragma unroll
        for (int k16 = 0; k16 < 32; k16 += 16) {
            unsigned af[4][4], bhf[4][2], blf[4][2];
            int arow = wm * 64 + (lane & 15);
            int acol = k16 + ((lane >> 4) << 3);
#pragma unroll
            for (int mt = 0; mt < 4; mt++) {
                unsigned p = (unsigned)__cvta_generic_to_shared(&Ah[arow + mt * 16][acol]);
                LDSM_X4(af[mt], p);
            }
            int brow = k16 + (lane & 15);
#pragma unroll
            for (int nt = 0; nt < 4; nt++) {
                int n0 = wn * 32 + nt * 8;
                unsigned ph = (unsigned)__cvta_generic_to_shared(&Bh[brow][n0]);
                unsigned pl = (unsigned)__cvta_generic_to_shared(&Bl[brow][n0]);
                LDSM_X2T(bhf[nt], ph);
                LDSM_X2T(blf[nt], pl);
            }
            // hi*hi
#pragma unroll
            for (int mt = 0; mt < 4; mt++)
#pragma unroll
                for (int nt = 0; nt < 4; nt++) MMA_BF16(acc[mt][nt], af[mt], bhf[nt]);
            // hi*lo
#pragma unroll
            for (int mt = 0; mt < 4; mt++)
#pragma unroll
                for (int nt = 0; nt < 4; nt++) MMA_BF16(acc[mt][nt], af[mt], blf[nt]);
            // lo*hi (reload A frags with lo)
#pragma unroll
            for (int mt = 0; mt < 4; mt++) {
                unsigned p = (unsigned)__cvta_generic_to_shared(&Al[arow + mt * 16][acol]);
                LDSM_X4(af[mt], p);
            }
#pragma unroll
            for (int mt = 0; mt < 4; mt++)
#pragma unroll
                for (int nt = 0; nt < 4; nt++) MMA_BF16(acc[mt][nt], af[mt], bhf[nt]);
        }
        __syncthreads();
    }

    // epilogue: C = acc + bias
    int r_base = bm + wm * 64;
    int c_base = bn + wn * 32;
#pragma unroll
    for (int nt = 0; nt < 4; nt++) {
        int col = c_base + nt * 8 + ((lane & 3) << 1);
        float2 bv = *(const float2*)(bias + col);
#pragma unroll
        for (int mt = 0; mt < 4; mt++) {
            int r0 = r_base + mt * 16 + (lane >> 2);
            if (r0 < M) {
                float2 o = make_float2(acc[mt][nt][0] + bv.x, acc[mt][nt][1] + bv.y);
                *(float2*)(C + (size_t)r0 * ldc + col) = o;
            }
            int r1 = r0 + 8;
            if (r1 < M) {
                float2 o = make_float2(acc[mt][nt][2] + bv.x, acc[mt][nt][3] + bv.y);
                *(float2*)(C + (size_t)r1 * ldc + col) = o;
            }
        }
    }
}

// ---------------- BatchNorm stats + apply + relu ----------------
__global__ void colstats_kernel() {
    int c = threadIdx.x;
    float s = 0.f, q = 0.f;
    for (int r = blockIdx.x; r < NN; r += gridDim.x) {
        float v = g_h[(size_t)r * DD + c];
        s += v;
        q += v * v;
    }
    atomicAdd(&g_colsum[c], s);
    atomicAdd(&g_colsq[c], q);
}

__global__ void bnrelu_kernel(const float* __restrict__ bg, const float* __restrict__ bb) {
    int i = blockIdx.x * blockDim.x + threadIdx.x;
    if (i >= NN * DD) return;
    int c = i & 127;
    float invn = 1.0f / (float)NN;
    float mu = g_colsum[c] * invn;
    float var = g_colsq[c] * invn - mu * mu;
    float v = (g_h[i] - mu) * rsqrtf(var + 1e-5f) * bg[c] + bb[c];
    g_h[i] = v > 0.f ? v : 0.f;
}

// ---------------- edge stage: one warp per dst node, single pass ----------------
// g_hy row: [xw(128) | y_r(128)*4]; online softmax anchored at first edge value
__global__ void edge_kernel() {
    int w = (blockIdx.x * blockDim.x + threadIdx.x) >> 5;
    if (w >= NN) return;
    int lane = threadIdx.x & 31;
    int c = lane << 2;
    int s0 = g_off[w], s1 = g_off[w + 1];
    float4 zo = make_float4(0.f, 0.f, 0.f, 0.f);
    if (s0 < s1) {
        int s = g_srcs[s0];
        int t = g_types[s0];
        float wnrm = g_norms[s0];
        const float* base = g_hy + (size_t)s * 640;
        float4 xj = *(const float4*)(base + c);
        float4 r = *(const float4*)(base + 128 + (t << 7) + c);
        float gx = xj.x * wnrm, gy = xj.y * wnrm, gz = xj.z * wnrm, gw = xj.w * wnrm;
        float mx = r.x, my = r.y, mz = r.z, mw = r.w;
        float dx = 1.f, dy = 1.f, dz = 1.f, dw = 1.f;
        float nx = r.x, ny = r.y, nz = r.z, nw = r.w;
        for (int e = s0 + 1; e < s1; e++) {
            s = g_srcs[e];
            t = g_types[e];
            wnrm = g_norms[e];
            base = g_hy + (size_t)s * 640;
            xj = *(const float4*)(base + c);
            r = *(const float4*)(base + 128 + (t << 7) + c);
            gx += xj.x * wnrm; gy += xj.y * wnrm; gz += xj.z * wnrm; gw += xj.w * wnrm;
            float ex = __expf(r.x - mx); dx += ex; nx += r.x * ex;
            float ey = __expf(r.y - my); dy += ey; ny += r.y * ey;
            float ez = __expf(r.z - mz); dz += ez; nz += r.z * ez;
            float ew = __expf(r.w - mw); dw += ew; nw += r.w * ew;
        }
        float m0 = nx / dx, m1 = ny / dy, m2 = nz / dz, m3 = nw / dw;
        zo.x = gx + 0.1f * fmaxf(m0, 0.f);
        zo.y = gy + 0.1f * fmaxf(m1, 0.f);
        zo.z = gz + 0.1f * fmaxf(m2, 0.f);
        zo.w = gw + 0.1f * fmaxf(m3, 0.f);
    }
    *(float4*)&g_z[((size_t)w << 7) + c] = zo;
}

// ---------------- final: exact gelu + gather at idx ----------------
__global__ void gelu_gather_kernel(const int* __restrict__ idx, float* __restrict__ out, int ni) {
    int i = blockIdx.x * blockDim.x + threadIdx.x;
    if (i >= ni * DD) return;
    int row = idx[i >> 7];
    float v = g_h[((size_t)row << 7) + (i & 127)];
    out[i] = 0.5f * v * (1.0f + erff(v * 0.70710678118654752f));
}

// ---------------- host launcher ----------------
static void* sym_addr(const void* sym) {
    void* p = nullptr;
    cudaGetSymbolAddress(&p, sym);
    return p;
}

extern "C" void kernel_launch(void* const* d_in, const int* in_sizes, int n_in,
                              void* d_out, int out_size) {
    int ix, iei, iidx, iet, ipw, ipb, ibg, ibb, iww, iwb, iwr, iow, iob;
    if (in_sizes[1] > 1000000) {
        // dict order
        ix = 0; iei = 1; iidx = 2; iet = 3; ipw = 5; ipb = 6; ibg = 7; ibb = 8;
        iww = 9; iwb = 10; iwr = 11; iow = 12; iob = 13;
    } else {
        // signature order
        ix = 0; ipw = 2; ipb = 3; ibg = 4; ibb = 5; iww = 6; iwb = 7;
        iwr = 8; iow = 9; iob = 10; iei = 11; iet = 12; iidx = 13;
    }

    const float* x   = (const float*)d_in[ix];
    const int*   ei  = (const int*)d_in[iei];
    const int*   et  = (const int*)d_in[iet];
    const int*   idx = (const int*)d_in[iidx];
    const float* pw  = (const float*)d_in[ipw];
    const float* pb  = (const float*)d_in[ipb];
    const float* bg  = (const float*)d_in[ibg];
    const float* bb  = (const float*)d_in[ibb];
    const float* ww  = (const float*)d_in[iww];
    const float* wb  = (const float*)d_in[iwb];
    const float* wr  = (const float*)d_in[iwr];
    const float* ow  = (const float*)d_in[iow];
    const float* ob  = (const float*)d_in[iob];

    int E  = in_sizes[iei] / 2;
    int NI = out_size / DD;

    float* hbuf  = (float*)sym_addr(g_h);
    float* hybuf = (float*)sym_addr(g_hy);
    float* zbuf  = (float*)sym_addr(g_z);
    float* wcbuf = (float*)sym_addr(g_wc);
    float* bcbuf = (float*)sym_addr(g_bc);

    // CSR build
    zero_kernel<<<(NN + 255) / 256, 256>>>();
    hist_kernel<<<(E + 255) / 256, 256>>>(ei, E);
    scan_kernel<<<1, 1024>>>(E);
    scatter_kernel<<<(E + 255) / 256, 256>>>(ei, et, E);

    // weight prep (combined weights + biases)
    prep_kernel<<<(32768 + 1280 + 255) / 256, 256>>>(ww, wb, wr);
    wc_kernel<<<dim3(8, 4), 256>>>(ww, wr);

    int mtiles = (NN + 127) / 128;   // 381

    // projection + batchnorm + relu
    gemm_split_kernel<<<dim3(1, mtiles), 256>>>(x, pw, pb, hbuf, NN, 128, 128);
    colstats_kernel<<<512, 128>>>();
    bnrelu_kernel<<<(NN * DD + 255) / 256, 256>>>(bg, bb);

    // two DAN layers
    for (int l = 0; l < 2; l++) {
        const float* low = ow + (size_t)l * DD * DD;
        const float* lob = ob + (size_t)l * DD;
        // [xw | y0..3] = h @ Wc + bc  (N=640)
        gemm_split_kernel<<<dim3(5, mtiles), 256>>>(hbuf, wcbuf + (size_t)l * 81920,
                                                    bcbuf + l * 640, hybuf, NN, 640, 640);
        // edge aggregation
        edge_kernel<<<(NN * 32 + 255) / 256, 256>>>();
        // h = z @ out_w + out_b
        gemm_split_kernel<<<dim3(1, mtiles), 256>>>(zbuf, low, lob, hbuf, NN, 128, 128);
    }

    // gelu(exact) + gather
    gelu_gather_kernel<<<(NI * DD + 255) / 256, 256>>>(idx, (float*)d_out, NI);
}

// round 3
// speedup vs baseline: 1.8190x; 1.3092x over previous
#include <cuda_runtime.h>
#include <cuda_bf16.h>
#include <math.h>

#define NN 48758
#define EMAX 780000
#define NB 48   // ceil(NN/1024)

// ---------------- device scratch ----------------
__device__ __align__(16) float g_h[(size_t)NN * 128];
__device__ __align__(16) __nv_bfloat16 g_hh[(size_t)NN * 128];
__device__ __align__(16) __nv_bfloat16 g_hl[(size_t)NN * 128];
__device__ __align__(16) __nv_bfloat16 g_xsh[(size_t)NN * 128];
__device__ __align__(16) __nv_bfloat16 g_xsl[(size_t)NN * 128];
__device__ __align__(16) __nv_bfloat16 g_zh[(size_t)NN * 128];
__device__ __align__(16) __nv_bfloat16 g_zl[(size_t)NN * 128];
__device__ __align__(16) float    g_xw[(size_t)NN * 128];
__device__ __align__(16) unsigned g_erp[(size_t)NN * 512];  // packed bf16x2 (er, p)
__device__ int   g_off[NN + 1];
__device__ int   g_cur[NN];
__device__ int   g_degsrc[NN];
__device__ int   g_degdst[NN];
__device__ float g_dinv[NN];
__device__ int   g_pk[EMAX];
__device__ int   g_bsum[64];
__device__ float g_colsum[128], g_colsq[128];
__device__ float g_wc0[128 * 640], g_wc1[128 * 640], g_w01[128 * 640];
__device__ float g_bc0[640], g_bc1[640], g_b01[640];
__device__ __nv_bfloat16 g_wc0h[128 * 640], g_wc0l[128 * 640];
__device__ __nv_bfloat16 g_w01h[128 * 640], g_w01l[128 * 640];
__device__ __nv_bfloat16 g_pwh[128 * 128], g_pwl[128 * 128];
__device__ __nv_bfloat16 g_owh[128 * 128], g_owl[128 * 128];

__device__ __forceinline__ float dinvf(int dg) {
    return dg > 0 ? rsqrtf((float)dg) : 0.0f;
}

// ---------------- CSR build ----------------
__global__ void zero_kernel() {
    int i = blockIdx.x * blockDim.x + threadIdx.x;
    if (i < NN) { g_degsrc[i] = 0; g_degdst[i] = 0; }
    if (i < 128) { g_colsum[i] = 0.0f; g_colsq[i] = 0.0f; }
}

__global__ void hist_kernel(const int* __restrict__ ei, int E) {
    int e = blockIdx.x * blockDim.x + threadIdx.x;
    if (e >= E) return;
    atomicAdd(&g_degdst[ei[e]], 1);
    atomicAdd(&g_degsrc[ei[E + e]], 1);
}

__global__ void dinv_kernel() {
    int i = blockIdx.x * blockDim.x + threadIdx.x;
    if (i < NN) g_dinv[i] = dinvf(g_degsrc[i]);
}

__global__ void scan1_kernel() {
    __shared__ int sm[1024];
    int tid = threadIdx.x;
    int i = blockIdx.x * 1024 + tid;
    int v = (i < NN) ? g_degdst[i] : 0;
    sm[tid] = v;
    __syncthreads();
    for (int ofs = 512; ofs > 0; ofs >>= 1) {
        if (tid < ofs) sm[tid] += sm[tid + ofs];
        __syncthreads();
    }
    if (tid == 0) g_bsum[blockIdx.x] = sm[0];
}

__global__ void scan2_kernel() {
    __shared__ int sm[64];
    int tid = threadIdx.x;   // 64 threads
    int v = (tid < NB) ? g_bsum[tid] : 0;
    sm[tid] = v;
    __syncthreads();
    for (int ofs = 1; ofs < 64; ofs <<= 1) {
        int t = (tid >= ofs) ? sm[tid - ofs] : 0;
        __syncthreads();
        sm[tid] += t;
        __syncthreads();
    }
    if (tid < NB) g_bsum[tid] = sm[tid] - v;   // exclusive
}

__global__ void scan3_kernel(int E) {
    __shared__ int sm[1024];
    int tid = threadIdx.x;
    int i = blockIdx.x * 1024 + tid;
    int v = (i < NN) ? g_degdst[i] : 0;
    sm[tid] = v;
    __syncthreads();
    for (int ofs = 1; ofs < 1024; ofs <<= 1) {
        int t = (tid >= ofs) ? sm[tid - ofs] : 0;
        __syncthreads();
        sm[tid] += t;
        __syncthreads();
    }
    int base = g_bsum[blockIdx.x];
    if (i < NN) {
        int exv = base + sm[tid] - v;
        g_off[i] = exv;
        g_cur[i] = exv;
        if (i == NN - 1) g_off[NN] = E;
    }
}

__global__ void scatter_kernel(const int* __restrict__ ei, const int* __restrict__ et, int E) {
    int e = blockIdx.x * blockDim.x + threadIdx.x;
    if (e >= E) return;
    int d = ei[e];
    int s = ei[E + e];
    int slot = atomicAdd(&g_cur[d], 1);
    g_pk[slot] = (s << 2) | et[e];
}

// ---------------- weight prep ----------------
// wc[l] = [win_l | win_l @ wrel_l_r], 128 x 640
__global__ void wprep1_kernel(const float* __restrict__ ww, const float* __restrict__ wr) {
    int i = blockIdx.x * blockDim.x + threadIdx.x;
    if (i >= 2 * 81920) return;
    int l = i / 81920, rem = i % 81920, k = rem / 640, n = rem % 640;
    float v;
    if (n < 128) {
        v = ww[l * 16384 + k * 128 + n];
    } else {
        int r = (n - 128) >> 7, nn = (n - 128) & 127;
        const float* a = ww + l * 16384 + k * 128;
        const float* b = wr + (size_t)((l * 4 + r) * 128) * 128 + nn;
        float s = 0.f;
        for (int j = 0; j < 128; j++) s += a[j] * b[(size_t)j * 128];
        v = s;
    }
    (l ? g_wc1 : g_wc0)[k * 640 + n] = v;
}

__global__ void bprep1_kernel(const float* __restrict__ wbv, const float* __restrict__ wr) {
    int i = blockIdx.x * blockDim.x + threadIdx.x;
    if (i >= 2 * 640) return;
    int l = i / 640, n = i % 640;
    float v;
    if (n < 128) {
        v = wbv[l * 128 + n];
    } else {
        int r = (n - 128) >> 7, nn = (n - 128) & 127;
        const float* a = wbv + l * 128;
        const float* b = wr + (size_t)((l * 4 + r) * 128) * 128 + nn;
        float s = 0.f;
        for (int j = 0; j < 128; j++) s += a[j] * b[(size_t)j * 128];
        v = s;
    }
    (l ? g_bc1 : g_bc0)[n] = v;
}

// W01 = ow0 @ wc1 ; b01 = ob0 @ wc1 + bc1
__global__ void wprep2_kernel(const float* __restrict__ ow) {
    int i = blockIdx.x * blockDim.x + threadIdx.x;
    if (i >= 81920) return;
    int k = i / 640, n = i % 640;
    const float* a = ow + k * 128;   // layer0 out_w
    float s = 0.f;
    for (int j = 0; j < 128; j++) s += a[j] * g_wc1[j * 640 + n];
    g_w01[k * 640 + n] = s;
}

__global__ void bprep2_kernel(const float* __restrict__ obv) {
    int n = blockIdx.x * blockDim.x + threadIdx.x;
    if (n >= 640) return;
    float s = 0.f;
    for (int j = 0; j < 128; j++) s += obv[j] * g_wc1[j * 640 + n];
    g_b01[n] = s + g_bc1[n];
}

__global__ void split_kernel(const float* __restrict__ s, __nv_bfloat16* __restrict__ dh,
                             __nv_bfloat16* __restrict__ dl, int n) {
    int i = blockIdx.x * blockDim.x + threadIdx.x;
    if (i >= n) return;
    float f = s[i];
    __nv_bfloat16 h = __float2bfloat16_rn(f);
    dh[i] = h;
    dl[i] = __float2bfloat16_rn(f - __bfloat162float(h));
}

// ---------------- tensor-core GEMM (pure pre-split bf16, 3xMMA) ----------------
#define LDSM_X4(R, p) asm volatile( \
    "ldmatrix.sync.aligned.m8n8.x4.shared.b16 {%0,%1,%2,%3}, [%4];" \
    : "=r"((R)[0]), "=r"((R)[1]), "=r"((R)[2]), "=r"((R)[3]) : "r"(p))
#define LDSM_X2T(R, p) asm volatile( \
    "ldmatrix.sync.aligned.m8n8.x2.trans.shared.b16 {%0,%1}, [%2];" \
    : "=r"((R)[0]), "=r"((R)[1]) : "r"(p))
#define MMA_BF16(d, a, b) asm volatile( \
    "mma.sync.aligned.m16n8k16.row.col.f32.bf16.bf16.f32 " \
    "{%0,%1,%2,%3},{%4,%5,%6,%7},{%8,%9},{%0,%1,%2,%3};" \
    : "+f"((d)[0]), "+f"((d)[1]), "+f"((d)[2]), "+f"((d)[3]) \
    : "r"((a)[0]), "r"((a)[1]), "r"((a)[2]), "r"((a)[3]), "r"((b)[0]), "r"((b)[1]))

__device__ __forceinline__ unsigned packerp(float v) {
    float er = __expf(v);
    float p = v * er;
    __nv_bfloat162 t = __halves2bfloat162(__float2bfloat16_rn(er), __float2bfloat16_rn(p));
    return *reinterpret_cast<unsigned*>(&t);
}

// MODE 0: C = acc + bias (fp32, ldc)
// MODE 1: bn==0 -> g_xw fp32 ; bn>0 -> g_erp packed(exp(v), v*exp(v))
// MODE 2: C = gelu(acc + bias), rows via ridx gather on A
template <int MODE>
__global__ __launch_bounds__(256, 2)
void gemm_bf16(const __nv_bfloat16* __restrict__ Ah, const __nv_bfloat16* __restrict__ Al,
               const __nv_bfloat16* __restrict__ Bh, const __nv_bfloat16* __restrict__ Bl,
               const float* __restrict__ bias, float* __restrict__ C,
               int M, int ldb, int ldc, const int* __restrict__ ridx) {
    __shared__ __align__(16) __nv_bfloat16 Ahs[128][40];
    __shared__ __align__(16) __nv_bfloat16 Als[128][40];
    __shared__ __align__(16) __nv_bfloat16 Bhs[32][136];
    __shared__ __align__(16) __nv_bfloat16 Bls[32][136];

    int tid = threadIdx.x, lane = tid & 31, warp = tid >> 5;
    int wm = warp >> 2, wn = warp & 3;
    int bm = blockIdx.y * 128, bn = blockIdx.x * 128;

    float acc[4][4][4];
#pragma unroll
    for (int a = 0; a < 4; a++)
#pragma unroll
        for (int b = 0; b < 4; b++)
#pragma unroll
            for (int c = 0; c < 4; c++) acc[a][b][c] = 0.0f;

    // A row remap (fixed across k iterations)
    int arr[2];
#pragma unroll
    for (int i = 0; i < 2; i++) {
        int row = (tid + i * 256) >> 2;
        int grow = bm + row;
        arr[i] = (grow < M) ? (ridx ? ridx[grow] : grow) : -1;
    }

    for (int k0 = 0; k0 < 128; k0 += 32) {
#pragma unroll
        for (int i = 0; i < 2; i++) {
            int vec = tid + i * 256;
            int row = vec >> 2;
            int c8 = (vec & 3) * 8;
            uint4 vh = make_uint4(0, 0, 0, 0), vl = make_uint4(0, 0, 0, 0);
            if (arr[i] >= 0) {
                size_t go = (size_t)arr[i] * 128 + k0 + c8;
                vh = *(const uint4*)(Ah + go);
                vl = *(const uint4*)(Al + go);
            }
            *(uint4*)&Ahs[row][c8] = vh;
            *(uint4*)&Als[row][c8] = vl;
        }
#pragma unroll
        for (int i = 0; i < 2; i++) {
            int vec = tid + i * 256;
            int row = vec >> 4;
            int c8 = (vec & 15) * 8;
            size_t go = (size_t)(k0 + row) * ldb + bn + c8;
            *(uint4*)&Bhs[row][c8] = *(const uint4*)(Bh + go);
            *(uint4*)&Bls[row][c8] = *(const uint4*)(Bl + go);
        }
        __syncthreads();

#pragma unroll
        for (int k16 = 0; k16 < 32; k16 += 16) {
            unsigned af[4][4], bhf[4][2], blf[4][2];
            int arow = wm * 64 + (lane & 15);
            int acol = k16 + ((lane >> 4) << 3);
#pragma unroll
            for (int mt = 0; mt < 4; mt++) {
                unsigned p = (unsigned)__cvta_generic_to_shared(&Ahs[arow + mt * 16][acol]);
                LDSM_X4(af[mt], p);
            }
            int brow = k16 + (lane & 15);
#pragma unroll
            for (int nt = 0; nt < 4; nt++) {
                int n0 = wn * 32 + nt * 8;
                unsigned ph = (unsigned)__cvta_generic_to_shared(&Bhs[brow][n0]);
                unsigned pl = (unsigned)__cvta_generic_to_shared(&Bls[brow][n0]);
                LDSM_X2T(bhf[nt], ph);
                LDSM_X2T(blf[nt], pl);
            }
#pragma unroll
            for (int mt = 0; mt < 4; mt++)
#pragma unroll
                for (int nt = 0; nt < 4; nt++) MMA_BF16(acc[mt][nt], af[mt], bhf[nt]);
#pragma unroll
            for (int mt = 0; mt < 4; mt++)
#pragma unroll
                for (int nt = 0; nt < 4; nt++) MMA_BF16(acc[mt][nt], af[mt], blf[nt]);
#pragma unroll
            for (int mt = 0; mt < 4; mt++) {
                unsigned p = (unsigned)__cvta_generic_to_shared(&Als[arow + mt * 16][acol]);
                LDSM_X4(af[mt], p);
            }
#pragma unroll
            for (int mt = 0; mt < 4; mt++)
#pragma unroll
                for (int nt = 0; nt < 4; nt++) MMA_BF16(acc[mt][nt], af[mt], bhf[nt]);
        }
        __syncthreads();
    }

    int r_base = bm + wm * 64;
#pragma unroll
    for (int nt = 0; nt < 4; nt++) {
        int cl = wn * 32 + nt * 8 + ((lane & 3) << 1);  // local col in [0,128)
        int cg = bn + cl;
        float2 bv = *(const float2*)(bias + cg);
#pragma unroll
        for (int mt = 0; mt < 4; mt++) {
            int r0 = r_base + mt * 16 + (lane >> 2);
            int r1 = r0 + 8;
            float v00 = acc[mt][nt][0] + bv.x, v01 = acc[mt][nt][1] + bv.y;
            float v10 = acc[mt][nt][2] + bv.x, v11 = acc[mt][nt][3] + bv.y;
            if (MODE == 0) {
                if (r0 < M) *(float2*)(C + (size_t)r0 * ldc + cg) = make_float2(v00, v01);
                if (r1 < M) *(float2*)(C + (size_t)r1 * ldc + cg) = make_float2(v10, v11);
            } else if (MODE == 1) {
                if (bn == 0) {
                    if (r0 < M) *(float2*)(g_xw + ((size_t)r0 << 7) + cl) = make_float2(v00, v01);
                    if (r1 < M) *(float2*)(g_xw + ((size_t)r1 << 7) + cl) = make_float2(v10, v11);
                } else {
                    int yc = cg - 128;
                    if (r0 < M) {
                        uint2 u = make_uint2(packerp(v00), packerp(v01));
                        *(uint2*)(g_erp + ((size_t)r0 << 9) + yc) = u;
                    }
                    if (r1 < M) {
                        uint2 u = make_uint2(packerp(v10), packerp(v11));
                        *(uint2*)(g_erp + ((size_t)r1 << 9) + yc) = u;
                    }
                }
            } else {
                if (r0 < M) {
                    float a = 0.5f * v00 * (1.0f + erff(v00 * 0.70710678118654752f));
                    float b = 0.5f * v01 * (1.0f + erff(v01 * 0.70710678118654752f));
                    *(float2*)(C + (size_t)r0 * ldc + cg) = make_float2(a, b);
                }
                if (r1 < M) {
                    float a = 0.5f * v10 * (1.0f + erff(v10 * 0.70710678118654752f));
                    float b = 0.5f * v11 * (1.0f + erff(v11 * 0.70710678118654752f));
                    *(float2*)(C + (size_t)r1 * ldc + cg) = make_float2(a, b);
                }
            }
        }
    }
}

// ---------------- BatchNorm ----------------
__global__ void colstats_kernel() {
    int c = threadIdx.x;
    float s = 0.f, q = 0.f;
    for (int r = blockIdx.x; r < NN; r += gridDim.x) {
        float v = g_h[((size_t)r << 7) + c];
        s += v;
        q += v * v;
    }
    atomicAdd(&g_colsum[c], s);
    atomicAdd(&g_colsq[c], q);
}

__global__ void bnrelu_kernel(const float* __restrict__ bg, const float* __restrict__ bb) {
    int i = blockIdx.x * blockDim.x + threadIdx.x;
    if (i >= NN * 128) return;
    int c = i & 127;
    float invn = 1.0f / (float)NN;
    float mu = g_colsum[c] * invn;
    float var = g_colsq[c] * invn - mu * mu;
    float v = (g_h[i] - mu) * rsqrtf(var + 1e-5f) * bg[c] + bb[c];
    v = fmaxf(v, 0.f);
    __nv_bfloat16 h = __float2bfloat16_rn(v);
    g_hh[i] = h;
    g_hl[i] = __float2bfloat16_rn(v - __bfloat162float(h));
}

// ---------------- edge stage: one warp per dst node, no transcendentals ----------------
__global__ void edge_kernel() {
    int w = (blockIdx.x * blockDim.x + threadIdx.x) >> 5;
    if (w >= NN) return;
    int lane = threadIdx.x & 31;
    int c = lane << 2;
    int s0 = g_off[w], s1 = g_off[w + 1];
    float4 z = make_float4(0.f, 0.f, 0.f, 0.f);
    if (s0 < s1) {
        float dd = g_dinv[w];
        float gx = 0.f, gy = 0.f, gz = 0.f, gw = 0.f;
        float d0 = 0.f, d1 = 0.f, d2 = 0.f, d3 = 0.f;
        float n0 = 0.f, n1 = 0.f, n2 = 0.f, n3 = 0.f;
        for (int e = s0; e < s1; e++) {
            int pk = __ldg(&g_pk[e]);
            int s = pk >> 2, t = pk & 3;
            float wn = dd * __ldg(&g_dinv[s]);
            float4 xj = *(const float4*)(g_xw + ((size_t)s << 7) + c);
            uint4 ep = *(const uint4*)(g_erp + ((size_t)s << 9) + (t << 7) + c);
            float2 a0 = __bfloat1622float2(*(__nv_bfloat162*)&ep.x);
            float2 a1 = __bfloat1622float2(*(__nv_bfloat162*)&ep.y);
            float2 a2 = __bfloat1622float2(*(__nv_bfloat162*)&ep.z);
            float2 a3 = __bfloat1622float2(*(__nv_bfloat162*)&ep.w);
            d0 += a0.x; n0 += a0.y;
            d1 += a1.x; n1 += a1.y;
            d2 += a2.x; n2 += a2.y;
            d3 += a3.x; n3 += a3.y;
            gx += xj.x * wn; gy += xj.y * wn; gz += xj.z * wn; gw += xj.w * wn;
        }
        z.x = gx + 0.1f * fmaxf(n0 / d0, 0.f);
        z.y = gy + 0.1f * fmaxf(n1 / d1, 0.f);
        z.z = gz + 0.1f * fmaxf(n2 / d2, 0.f);
        z.w = gw + 0.1f * fmaxf(n3 / d3, 0.f);
    }
    // split store
    __nv_bfloat16 h0 = __float2bfloat16_rn(z.x), h1 = __float2bfloat16_rn(z.y);
    __nv_bfloat16 h2 = __float2bfloat16_rn(z.z), h3 = __float2bfloat16_rn(z.w);
    __nv_bfloat16 l0 = __float2bfloat16_rn(z.x - __bfloat162float(h0));
    __nv_bfloat16 l1 = __float2bfloat16_rn(z.y - __bfloat162float(h1));
    __nv_bfloat16 l2 = __float2bfloat16_rn(z.z - __bfloat162float(h2));
    __nv_bfloat16 l3 = __float2bfloat16_rn(z.w - __bfloat162float(h3));
    __nv_bfloat162 ph0 = __halves2bfloat162(h0, h1), ph1 = __halves2bfloat162(h2, h3);
    __nv_bfloat162 pl0 = __halves2bfloat162(l0, l1), pl1 = __halves2bfloat162(l2, l3);
    size_t o = ((size_t)w << 7) + c;
    *(uint2*)(g_zh + o) = make_uint2(*(unsigned*)&ph0, *(unsigned*)&ph1);
    *(uint2*)(g_zl + o) = make_uint2(*(unsigned*)&pl0, *(unsigned*)&pl1);
}

// ---------------- host launcher ----------------
static void* sym_addr(const void* sym) {
    void* p = nullptr;
    cudaGetSymbolAddress(&p, sym);
    return p;
}

extern "C" void kernel_launch(void* const* d_in, const int* in_sizes, int n_in,
                              void* d_out, int out_size) {
    int ix, iei, iidx, iet, ipw, ipb, ibg, ibb, iww, iwb, iwr, iow, iob;
    if (in_sizes[1] > 1000000) {
        ix = 0; iei = 1; iidx = 2; iet = 3; ipw = 5; ipb = 6; ibg = 7; ibb = 8;
        iww = 9; iwb = 10; iwr = 11; iow = 12; iob = 13;
    } else {
        ix = 0; ipw = 2; ipb = 3; ibg = 4; ibb = 5; iww = 6; iwb = 7;
        iwr = 8; iow = 9; iob = 10; iei = 11; iet = 12; iidx = 13;
    }

    const float* x   = (const float*)d_in[ix];
    const int*   ei  = (const int*)d_in[iei];
    const int*   et  = (const int*)d_in[iet];
    const int*   idx = (const int*)d_in[iidx];
    const float* pw  = (const float*)d_in[ipw];
    const float* pb  = (const float*)d_in[ipb];
    const float* bg  = (const float*)d_in[ibg];
    const float* bb  = (const float*)d_in[ibb];
    const float* ww  = (const float*)d_in[iww];
    const float* wb  = (const float*)d_in[iwb];
    const float* wr  = (const float*)d_in[iwr];
    const float* ow  = (const float*)d_in[iow];
    const float* ob  = (const float*)d_in[iob];

    int E  = in_sizes[iei] / 2;
    int NI = out_size / 128;

    float* hbuf  = (float*)sym_addr(g_h);
    __nv_bfloat16* hh  = (__nv_bfloat16*)sym_addr(g_hh);
    __nv_bfloat16* hl  = (__nv_bfloat16*)sym_addr(g_hl);
    __nv_bfloat16* xsh = (__nv_bfloat16*)sym_addr(g_xsh);
    __nv_bfloat16* xsl = (__nv_bfloat16*)sym_addr(g_xsl);
    __nv_bfloat16* zh  = (__nv_bfloat16*)sym_addr(g_zh);
    __nv_bfloat16* zl  = (__nv_bfloat16*)sym_addr(g_zl);
    float* wc0 = (float*)sym_addr(g_wc0);
    float* w01 = (float*)sym_addr(g_w01);
    float* bc0 = (float*)sym_addr(g_bc0);
    float* b01 = (float*)sym_addr(g_b01);
    __nv_bfloat16* wc0h = (__nv_bfloat16*)sym_addr(g_wc0h);
    __nv_bfloat16* wc0l = (__nv_bfloat16*)sym_addr(g_wc0l);
    __nv_bfloat16* w01h = (__nv_bfloat16*)sym_addr(g_w01h);
    __nv_bfloat16* w01l = (__nv_bfloat16*)sym_addr(g_w01l);
    __nv_bfloat16* pwh = (__nv_bfloat16*)sym_addr(g_pwh);
    __nv_bfloat16* pwl = (__nv_bfloat16*)sym_addr(g_pwl);
    __nv_bfloat16* owh = (__nv_bfloat16*)sym_addr(g_owh);
    __nv_bfloat16* owl = (__nv_bfloat16*)sym_addr(g_owl);

    // CSR build
    zero_kernel<<<(NN + 255) / 256, 256>>>();
    hist_kernel<<<(E + 255) / 256, 256>>>(ei, E);
    dinv_kernel<<<(NN + 255) / 256, 256>>>();
    scan1_kernel<<<NB, 1024>>>();
    scan2_kernel<<<1, 64>>>();
    scan3_kernel<<<NB, 1024>>>(E);
    scatter_kernel<<<(E + 255) / 256, 256>>>(ei, et, E);

    // weight prep
    wprep1_kernel<<<(2 * 81920 + 255) / 256, 256>>>(ww, wr);
    bprep1_kernel<<<(2 * 640 + 255) / 256, 256>>>(wb, wr);
    wprep2_kernel<<<(81920 + 255) / 256, 256>>>(ow);
    bprep2_kernel<<<(640 + 255) / 256, 256>>>(ob);
    split_kernel<<<(81920 + 255) / 256, 256>>>(wc0, wc0h, wc0l, 81920);
    split_kernel<<<(81920 + 255) / 256, 256>>>(w01, w01h, w01l, 81920);
    split_kernel<<<(16384 + 255) / 256, 256>>>(pw, pwh, pwl, 16384);
    split_kernel<<<(16384 + 255) / 256, 256>>>(ow + 16384, owh, owl, 16384);
    split_kernel<<<(NN * 128 + 255) / 256, 256>>>(x, xsh, xsl, NN * 128);

    int mtiles = (NN + 127) / 128;   // 381

    // projection + batchnorm + relu (write split h)
    gemm_bf16<0><<<dim3(1, mtiles), 256>>>(xsh, xsl, pwh, pwl, pb, hbuf, NN, 128, 128, nullptr);
    colstats_kernel<<<512, 128>>>();
    bnrelu_kernel<<<(NN * 128 + 255) / 256, 256>>>(bg, bb);

    // layer 0: [xw | erp] = h @ Wc0 + bc0
    gemm_bf16<1><<<dim3(5, mtiles), 256>>>(hh, hl, wc0h, wc0l, bc0, nullptr, NN, 640, 0, nullptr);
    edge_kernel<<<(NN * 32 + 255) / 256, 256>>>();

    // layer 1 (fused with layer0 out): [xw | erp] = z0 @ W01 + b01
    gemm_bf16<1><<<dim3(5, mtiles), 256>>>(zh, zl, w01h, w01l, b01, nullptr, NN, 640, 0, nullptr);
    edge_kernel<<<(NN * 32 + 255) / 256, 256>>>();

    // final: out = gelu(z1[idx] @ out_w1 + ob1)
    gemm_bf16<2><<<dim3(1, (NI + 127) / 128), 256>>>(zh, zl, owh, owl, ob + 128, (float*)d_out,
                                                     NI, 128, 128, idx);
}

// round 4
// speedup vs baseline: 2.0332x; 1.1178x over previous
#include <cuda_runtime.h>
#include <cuda_bf16.h>
#include <math.h>

#define NN 48758
#define EMAX 780000
#define NB 48   // ceil(NN/1024)

// ---------------- device scratch ----------------
__device__ __align__(16) float g_h[(size_t)NN * 128];
__device__ __align__(16) __nv_bfloat16 g_hh[(size_t)NN * 128];
__device__ __align__(16) __nv_bfloat16 g_hl[(size_t)NN * 128];
__device__ __align__(16) __nv_bfloat16 g_xsh[(size_t)NN * 128];
__device__ __align__(16) __nv_bfloat16 g_xsl[(size_t)NN * 128];
__device__ __align__(16) __nv_bfloat16 g_zh[(size_t)NN * 128];
__device__ __align__(16) __nv_bfloat16 g_zl[(size_t)NN * 128];
__device__ __align__(16) float    g_xw[(size_t)NN * 128];
__device__ __align__(16) unsigned g_erp[(size_t)NN * 512];  // packed bf16x2 (er, p)
__device__ int   g_off[NN + 1];
__device__ int   g_cur[NN];
__device__ int   g_degsrc[NN];
__device__ int   g_degdst[NN];
__device__ float g_dinv[NN];
__device__ int   g_pk[EMAX];
__device__ float g_nrm[EMAX];
__device__ int   g_bsum[64];
__device__ float g_colsum[128], g_colsq[128];
__device__ float g_wc1[128 * 640];
__device__ float g_bc0[640], g_bc1[640], g_b01[640];
__device__ __nv_bfloat16 g_wc0h[128 * 640], g_wc0l[128 * 640];
__device__ __nv_bfloat16 g_w01h[128 * 640], g_w01l[128 * 640];
__device__ __nv_bfloat16 g_pwh[128 * 128], g_pwl[128 * 128];
__device__ __nv_bfloat16 g_owh[128 * 128], g_owl[128 * 128];

__device__ __forceinline__ float dinvf(int dg) {
    return dg > 0 ? rsqrtf((float)dg) : 0.0f;
}

// ---------------- CSR build ----------------
__global__ void zero_kernel() {
    int i = blockIdx.x * blockDim.x + threadIdx.x;
    if (i < NN) { g_degsrc[i] = 0; g_degdst[i] = 0; }
    if (i < 128) { g_colsum[i] = 0.0f; g_colsq[i] = 0.0f; }
}

__global__ void hist_kernel(const int* __restrict__ ei, int E) {
    int e = blockIdx.x * blockDim.x + threadIdx.x;
    if (e >= E) return;
    atomicAdd(&g_degdst[ei[e]], 1);
    atomicAdd(&g_degsrc[ei[E + e]], 1);
}

__global__ void dinv_kernel() {
    int i = blockIdx.x * blockDim.x + threadIdx.x;
    if (i < NN) g_dinv[i] = dinvf(g_degsrc[i]);
}

__global__ void scan1_kernel() {
    __shared__ int sm[1024];
    int tid = threadIdx.x;
    int i = blockIdx.x * 1024 + tid;
    int v = (i < NN) ? g_degdst[i] : 0;
    sm[tid] = v;
    __syncthreads();
    for (int ofs = 512; ofs > 0; ofs >>= 1) {
        if (tid < ofs) sm[tid] += sm[tid + ofs];
        __syncthreads();
    }
    if (tid == 0) g_bsum[blockIdx.x] = sm[0];
}

__global__ void scan2_kernel() {
    __shared__ int sm[64];
    int tid = threadIdx.x;
    int v = (tid < NB) ? g_bsum[tid] : 0;
    sm[tid] = v;
    __syncthreads();
    for (int ofs = 1; ofs < 64; ofs <<= 1) {
        int t = (tid >= ofs) ? sm[tid - ofs] : 0;
        __syncthreads();
        sm[tid] += t;
        __syncthreads();
    }
    if (tid < NB) g_bsum[tid] = sm[tid] - v;
}

__global__ void scan3_kernel(int E) {
    __shared__ int sm[1024];
    int tid = threadIdx.x;
    int i = blockIdx.x * 1024 + tid;
    int v = (i < NN) ? g_degdst[i] : 0;
    sm[tid] = v;
    __syncthreads();
    for (int ofs = 1; ofs < 1024; ofs <<= 1) {
        int t = (tid >= ofs) ? sm[tid - ofs] : 0;
        __syncthreads();
        sm[tid] += t;
        __syncthreads();
    }
    int base = g_bsum[blockIdx.x];
    if (i < NN) {
        int exv = base + sm[tid] - v;
        g_off[i] = exv;
        g_cur[i] = exv;
        if (i == NN - 1) g_off[NN] = E;
    }
}

__global__ void scatter_kernel(const int* __restrict__ ei, const int* __restrict__ et, int E) {
    int e = blockIdx.x * blockDim.x + threadIdx.x;
    if (e >= E) return;
    int d = ei[e];
    int s = ei[E + e];
    int slot = atomicAdd(&g_cur[d], 1);
    g_pk[slot] = (s << 2) | et[e];
    g_nrm[slot] = g_dinv[d] * g_dinv[s];
}

// ---------------- weight prep ----------------
__device__ __forceinline__ void split_write(__nv_bfloat16* dh, __nv_bfloat16* dl, int i, float f) {
    __nv_bfloat16 h = __float2bfloat16_rn(f);
    dh[i] = h;
    dl[i] = __float2bfloat16_rn(f - __bfloat162float(h));
}

// wc[l] = [win_l | win_l @ wrel_l_r]; l=0 -> split bf16, l=1 -> fp32 (consumed by wprep2)
__global__ void wprep1_kernel(const float* __restrict__ ww, const float* __restrict__ wr) {
    int i = blockIdx.x * blockDim.x + threadIdx.x;
    if (i >= 2 * 81920) return;
    int l = i / 81920, rem = i % 81920, k = rem / 640, n = rem % 640;
    float v;
    if (n < 128) {
        v = ww[l * 16384 + k * 128 + n];
    } else {
        int r = (n - 128) >> 7, nn = (n - 128) & 127;
        const float* a = ww + l * 16384 + k * 128;
        const float* b = wr + (size_t)((l * 4 + r) * 128) * 128 + nn;
        float s = 0.f;
        for (int j = 0; j < 128; j++) s += a[j] * b[(size_t)j * 128];
        v = s;
    }
    if (l) g_wc1[rem] = v;
    else   split_write(g_wc0h, g_wc0l, rem, v);
}

__global__ void bprep1_kernel(const float* __restrict__ wbv, const float* __restrict__ wr) {
    int i = blockIdx.x * blockDim.x + threadIdx.x;
    if (i >= 2 * 640) return;
    int l = i / 640, n = i % 640;
    float v;
    if (n < 128) {
        v = wbv[l * 128 + n];
    } else {
        int r = (n - 128) >> 7, nn = (n - 128) & 127;
        const float* a = wbv + l * 128;
        const float* b = wr + (size_t)((l * 4 + r) * 128) * 128 + nn;
        float s = 0.f;
        for (int j = 0; j < 128; j++) s += a[j] * b[(size_t)j * 128];
        v = s;
    }
    (l ? g_bc1 : g_bc0)[n] = v;
}

// W01 = ow0 @ wc1 (split out) ; b01 = ob0 @ wc1 + bc1
__global__ void wprep2_kernel(const float* __restrict__ ow) {
    int i = blockIdx.x * blockDim.x + threadIdx.x;
    if (i >= 81920) return;
    int k = i / 640, n = i % 640;
    const float* a = ow + k * 128;
    float s = 0.f;
    for (int j = 0; j < 128; j++) s += a[j] * g_wc1[j * 640 + n];
    split_write(g_w01h, g_w01l, i, s);
}

__global__ void bprep2_kernel(const float* __restrict__ obv) {
    int n = blockIdx.x * blockDim.x + threadIdx.x;
    if (n >= 640) return;
    float s = 0.f;
    for (int j = 0; j < 128; j++) s += obv[j] * g_wc1[j * 640 + n];
    g_b01[n] = s + g_bc1[n];
}

__global__ void split_kernel(const float* __restrict__ s, __nv_bfloat16* __restrict__ dh,
                             __nv_bfloat16* __restrict__ dl, int n) {
    int i = blockIdx.x * blockDim.x + threadIdx.x;
    if (i >= n) return;
    float f = s[i];
    __nv_bfloat16 h = __float2bfloat16_rn(f);
    dh[i] = h;
    dl[i] = __float2bfloat16_rn(f - __bfloat162float(h));
}

// ---------------- tensor-core GEMM (pre-split bf16, 3xMMA, cp.async pipeline) ----------------
#define LDSM_X4(R, p) asm volatile( \
    "ldmatrix.sync.aligned.m8n8.x4.shared.b16 {%0,%1,%2,%3}, [%4];" \
    : "=r"((R)[0]), "=r"((R)[1]), "=r"((R)[2]), "=r"((R)[3]) : "r"(p))
#define LDSM_X2T(R, p) asm volatile( \
    "ldmatrix.sync.aligned.m8n8.x2.trans.shared.b16 {%0,%1}, [%2];" \
    : "=r"((R)[0]), "=r"((R)[1]) : "r"(p))
#define MMA_BF16(d, a, b) asm volatile( \
    "mma.sync.aligned.m16n8k16.row.col.f32.bf16.bf16.f32 " \
    "{%0,%1,%2,%3},{%4,%5,%6,%7},{%8,%9},{%0,%1,%2,%3};" \
    : "+f"((d)[0]), "+f"((d)[1]), "+f"((d)[2]), "+f"((d)[3]) \
    : "r"((a)[0]), "r"((a)[1]), "r"((a)[2]), "r"((a)[3]), "r"((b)[0]), "r"((b)[1]))

__device__ __forceinline__ void cpa16(void* dst, const void* src, int sz) {
    unsigned d = (unsigned)__cvta_generic_to_shared(dst);
    asm volatile("cp.async.cg.shared.global [%0], [%1], 16, %2;" :: "r"(d), "l"(src), "r"(sz));
}
__device__ __forceinline__ void cpa_commit() { asm volatile("cp.async.commit_group;"); }

__device__ __forceinline__ unsigned packerp(float v) {
    float er = __expf(v);
    float p = v * er;
    __nv_bfloat162 t = __halves2bfloat162(__float2bfloat16_rn(er), __float2bfloat16_rn(p));
    return *reinterpret_cast<unsigned*>(&t);
}

// MODE 0: C = acc + bias (fp32, ldc)
// MODE 1: bn==0 -> g_xw fp32 ; bn>0 -> g_erp packed(exp(v), v*exp(v))
// MODE 2: C = gelu(acc + bias), rows via ridx gather on A
template <int MODE>
__global__ __launch_bounds__(256, 2)
void gemm_bf16(const __nv_bfloat16* __restrict__ Ah, const __nv_bfloat16* __restrict__ Al,
               const __nv_bfloat16* __restrict__ Bh, const __nv_bfloat16* __restrict__ Bl,
               const float* __restrict__ bias, float* __restrict__ C,
               int M, int ldb, int ldc, const int* __restrict__ ridx) {
    __shared__ __align__(16) __nv_bfloat16 Ahs[2][128][40];
    __shared__ __align__(16) __nv_bfloat16 Als[2][128][40];
    __shared__ __align__(16) __nv_bfloat16 Bhs[2][32][136];
    __shared__ __align__(16) __nv_bfloat16 Bls[2][32][136];

    int tid = threadIdx.x, lane = tid & 31, warp = tid >> 5;
    int wm = warp >> 2, wn = warp & 3;
    int bm = blockIdx.y * 128, bn = blockIdx.x * 128;

    float acc[4][4][4];
#pragma unroll
    for (int a = 0; a < 4; a++)
#pragma unroll
        for (int b = 0; b < 4; b++)
#pragma unroll
            for (int c = 0; c < 4; c++) acc[a][b][c] = 0.0f;

    // A row remap + validity (fixed across k)
    int arr[2], asz[2];
#pragma unroll
    for (int i = 0; i < 2; i++) {
        int row = (tid + i * 256) >> 2;
        int grow = bm + row;
        bool ok = grow < M;
        arr[i] = ok ? (ridx ? ridx[grow] : grow) : 0;
        asz[i] = ok ? 16 : 0;
    }

    // async load of one BK=32 chunk into stage st
#define LOAD_CHUNK(st, k0)                                                        \
    {                                                                             \
        _Pragma("unroll")                                                         \
        for (int i = 0; i < 2; i++) {                                             \
            int vec = tid + i * 256;                                              \
            int row = vec >> 2;                                                   \
            int c8 = (vec & 3) * 8;                                               \
            size_t go = (size_t)arr[i] * 128 + (k0) + c8;                         \
            cpa16(&Ahs[st][row][c8], Ah + go, asz[i]);                            \
            cpa16(&Als[st][row][c8], Al + go, asz[i]);                            \
        }                                                                         \
        _Pragma("unroll")                                                         \
        for (int i = 0; i < 2; i++) {                                             \
            int vec = tid + i * 256;                                              \
            int row = vec >> 4;                                                   \
            int c8 = (vec & 15) * 8;                                              \
            size_t go = (size_t)((k0) + row) * ldb + bn + c8;                     \
            cpa16(&Bhs[st][row][c8], Bh + go, 16);                                \
            cpa16(&Bls[st][row][c8], Bl + go, 16);                                \
        }                                                                         \
        cpa_commit();                                                             \
    }

    LOAD_CHUNK(0, 0)
    LOAD_CHUNK(1, 32)

#pragma unroll
    for (int k0i = 0; k0i < 4; k0i++) {
        int st = k0i & 1;
        if (k0i < 3) asm volatile("cp.async.wait_group 1;");
        else         asm volatile("cp.async.wait_group 0;");
        __syncthreads();

#pragma unroll
        for (int k16 = 0; k16 < 32; k16 += 16) {
            unsigned af[4][4], bhf[4][2], blf[4][2];
            int arow = wm * 64 + (lane & 15);
            int acol = k16 + ((lane >> 4) << 3);
#pragma unroll
            for (int mt = 0; mt < 4; mt++) {
                unsigned p = (unsigned)__cvta_generic_to_shared(&Ahs[st][arow + mt * 16][acol]);
                LDSM_X4(af[mt], p);
            }
            int brow = k16 + (lane & 15);
#pragma unroll
            for (int nt = 0; nt < 4; nt++) {
                int n0 = wn * 32 + nt * 8;
                unsigned ph = (unsigned)__cvta_generic_to_shared(&Bhs[st][brow][n0]);
                unsigned pl = (unsigned)__cvta_generic_to_shared(&Bls[st][brow][n0]);
                LDSM_X2T(bhf[nt], ph);
                LDSM_X2T(blf[nt], pl);
            }
#pragma unroll
            for (int mt = 0; mt < 4; mt++)
#pragma unroll
                for (int nt = 0; nt < 4; nt++) MMA_BF16(acc[mt][nt], af[mt], bhf[nt]);
#pragma unroll
            for (int mt = 0; mt < 4; mt++)
#pragma unroll
                for (int nt = 0; nt < 4; nt++) MMA_BF16(acc[mt][nt], af[mt], blf[nt]);
#pragma unroll
            for (int mt = 0; mt < 4; mt++) {
                unsigned p = (unsigned)__cvta_generic_to_shared(&Als[st][arow + mt * 16][acol]);
                LDSM_X4(af[mt], p);
            }
#pragma unroll
            for (int mt = 0; mt < 4; mt++)
#pragma unroll
                for (int nt = 0; nt < 4; nt++) MMA_BF16(acc[mt][nt], af[mt], bhf[nt]);
        }
        __syncthreads();
        if (k0i < 2) LOAD_CHUNK(st, (k0i + 2) * 32)
    }

    int r_base = bm + wm * 64;
#pragma unroll
    for (int nt = 0; nt < 4; nt++) {
        int cl = wn * 32 + nt * 8 + ((lane & 3) << 1);
        int cg = bn + cl;
        float2 bv = *(const float2*)(bias + cg);
#pragma unroll
        for (int mt = 0; mt < 4; mt++) {
            int r0 = r_base + mt * 16 + (lane >> 2);
            int r1 = r0 + 8;
            float v00 = acc[mt][nt][0] + bv.x, v01 = acc[mt][nt][1] + bv.y;
            float v10 = acc[mt][nt][2] + bv.x, v11 = acc[mt][nt][3] + bv.y;
            if (MODE == 0) {
                if (r0 < M) *(float2*)(C + (size_t)r0 * ldc + cg) = make_float2(v00, v01);
                if (r1 < M) *(float2*)(C + (size_t)r1 * ldc + cg) = make_float2(v10, v11);
            } else if (MODE == 1) {
                if (bn == 0) {
                    if (r0 < M) *(float2*)(g_xw + ((size_t)r0 << 7) + cl) = make_float2(v00, v01);
                    if (r1 < M) *(float2*)(g_xw + ((size_t)r1 << 7) + cl) = make_float2(v10, v11);
                } else {
                    int yc = cg - 128;
                    if (r0 < M) {
                        uint2 u = make_uint2(packerp(v00), packerp(v01));
                        *(uint2*)(g_erp + ((size_t)r0 << 9) + yc) = u;
                    }
                    if (r1 < M) {
                        uint2 u = make_uint2(packerp(v10), packerp(v11));
                        *(uint2*)(g_erp + ((size_t)r1 << 9) + yc) = u;
                    }
                }
            } else {
                if (r0 < M) {
                    float a = 0.5f * v00 * (1.0f + erff(v00 * 0.70710678118654752f));
                    float b = 0.5f * v01 * (1.0f + erff(v01 * 0.70710678118654752f));
                    *(float2*)(C + (size_t)r0 * ldc + cg) = make_float2(a, b);
                }
                if (r1 < M) {
                    float a = 0.5f * v10 * (1.0f + erff(v10 * 0.70710678118654752f));
                    float b = 0.5f * v11 * (1.0f + erff(v11 * 0.70710678118654752f));
                    *(float2*)(C + (size_t)r1 * ldc + cg) = make_float2(a, b);
                }
            }
        }
    }
#undef LOAD_CHUNK
}

// ---------------- BatchNorm ----------------
__global__ void colstats_kernel() {
    int c = threadIdx.x;
    float s = 0.f, q = 0.f;
    for (int r = blockIdx.x; r < NN; r += gridDim.x) {
        float v = g_h[((size_t)r << 7) + c];
        s += v;
        q += v * v;
    }
    atomicAdd(&g_colsum[c], s);
    atomicAdd(&g_colsq[c], q);
}

__global__ void bnrelu_kernel(const float* __restrict__ bg, const float* __restrict__ bb) {
    int i = blockIdx.x * blockDim.x + threadIdx.x;
    if (i >= NN * 128) return;
    int c = i & 127;
    float invn = 1.0f / (float)NN;
    float mu = g_colsum[c] * invn;
    float var = g_colsq[c] * invn - mu * mu;
    float v = (g_h[i] - mu) * rsqrtf(var + 1e-5f) * bg[c] + bb[c];
    v = fmaxf(v, 0.f);
    __nv_bfloat16 h = __float2bfloat16_rn(v);
    g_hh[i] = h;
    g_hl[i] = __float2bfloat16_rn(v - __bfloat162float(h));
}

// ---------------- edge stage ----------------
__global__ void edge_kernel() {
    int w = (blockIdx.x * blockDim.x + threadIdx.x) >> 5;
    if (w >= NN) return;
    int lane = threadIdx.x & 31;
    int c = lane << 2;
    int s0 = g_off[w], s1 = g_off[w + 1];
    float4 z = make_float4(0.f, 0.f, 0.f, 0.f);
    if (s0 < s1) {
        float gx = 0.f, gy = 0.f, gz = 0.f, gw = 0.f;
        float d0 = 0.f, d1 = 0.f, d2 = 0.f, d3 = 0.f;
        float n0 = 0.f, n1 = 0.f, n2 = 0.f, n3 = 0.f;
        for (int e = s0; e < s1; e++) {
            int pk = __ldg(&g_pk[e]);
            float wn = __ldg(&g_nrm[e]);
            int s = pk >> 2, t = pk & 3;
            float4 xj = *(const float4*)(g_xw + ((size_t)s << 7) + c);
            uint4 ep = *(const uint4*)(g_erp + ((size_t)s << 9) + (t << 7) + c);
            float2 a0 = __bfloat1622float2(*(__nv_bfloat162*)&ep.x);
            float2 a1 = __bfloat1622float2(*(__nv_bfloat162*)&ep.y);
            float2 a2 = __bfloat1622float2(*(__nv_bfloat162*)&ep.z);
            float2 a3 = __bfloat1622float2(*(__nv_bfloat162*)&ep.w);
            d0 += a0.x; n0 += a0.y;
            d1 += a1.x; n1 += a1.y;
            d2 += a2.x; n2 += a2.y;
            d3 += a3.x; n3 += a3.y;
            gx += xj.x * wn; gy += xj.y * wn; gz += xj.z * wn; gw += xj.w * wn;
        }
        z.x = gx + 0.1f * fmaxf(n0 / d0, 0.f);
        z.y = gy + 0.1f * fmaxf(n1 / d1, 0.f);
        z.z = gz + 0.1f * fmaxf(n2 / d2, 0.f);
        z.w = gw + 0.1f * fmaxf(n3 / d3, 0.f);
    }
    __nv_bfloat16 h0 = __float2bfloat16_rn(z.x), h1 = __float2bfloat16_rn(z.y);
    __nv_bfloat16 h2 = __float2bfloat16_rn(z.z), h3 = __float2bfloat16_rn(z.w);
    __nv_bfloat16 l0 = __float2bfloat16_rn(z.x - __bfloat162float(h0));
    __nv_bfloat16 l1 = __float2bfloat16_rn(z.y - __bfloat162float(h1));
    __nv_bfloat16 l2 = __float2bfloat16_rn(z.z - __bfloat162float(h2));
    __nv_bfloat16 l3 = __float2bfloat16_rn(z.w - __bfloat162float(h3));
    __nv_bfloat162 ph0 = __halves2bfloat162(h0, h1), ph1 = __halves2bfloat162(h2, h3);
    __nv_bfloat162 pl0 = __halves2bfloat162(l0, l1), pl1 = __halves2bfloat162(l2, l3);
    size_t o = ((size_t)w << 7) + c;
    *(uint2*)(g_zh + o) = make_uint2(*(unsigned*)&ph0, *(unsigned*)&ph1);
    *(uint2*)(g_zl + o) = make_uint2(*(unsigned*)&pl0, *(unsigned*)&pl1);
}

// ---------------- host launcher ----------------
static void* sym_addr(const void* sym) {
    void* p = nullptr;
    cudaGetSymbolAddress(&p, sym);
    return p;
}

extern "C" void kernel_launch(void* const* d_in, const int* in_sizes, int n_in,
                              void* d_out, int out_size) {
    int ix, iei, iidx, iet, ipw, ipb, ibg, ibb, iww, iwb, iwr, iow, iob;
    if (in_sizes[1] > 1000000) {
        ix = 0; iei = 1; iidx = 2; iet = 3; ipw = 5; ipb = 6; ibg = 7; ibb = 8;
        iww = 9; iwb = 10; iwr = 11; iow = 12; iob = 13;
    } else {
        ix = 0; ipw = 2; ipb = 3; ibg = 4; ibb = 5; iww = 6; iwb = 7;
        iwr = 8; iow = 9; iob = 10; iei = 11; iet = 12; iidx = 13;
    }

    const float* x   = (const float*)d_in[ix];
    const int*   ei  = (const int*)d_in[iei];
    const int*   et  = (const int*)d_in[iet];
    const int*   idx = (const int*)d_in[iidx];
    const float* pw  = (const float*)d_in[ipw];
    const float* pb  = (const float*)d_in[ipb];
    const float* bg  = (const float*)d_in[ibg];
    const float* bb  = (const float*)d_in[ibb];
    const float* ww  = (const float*)d_in[iww];
    const float* wb  = (const float*)d_in[iwb];
    const float* wr  = (const float*)d_in[iwr];
    const float* ow  = (const float*)d_in[iow];
    const float* ob  = (const float*)d_in[iob];

    int E  = in_sizes[iei] / 2;
    int NI = out_size / 128;

    float* hbuf  = (float*)sym_addr(g_h);
    __nv_bfloat16* hh  = (__nv_bfloat16*)sym_addr(g_hh);
    __nv_bfloat16* hl  = (__nv_bfloat16*)sym_addr(g_hl);
    __nv_bfloat16* xsh = (__nv_bfloat16*)sym_addr(g_xsh);
    __nv_bfloat16* xsl = (__nv_bfloat16*)sym_addr(g_xsl);
    __nv_bfloat16* zh  = (__nv_bfloat16*)sym_addr(g_zh);
    __nv_bfloat16* zl  = (__nv_bfloat16*)sym_addr(g_zl);
    float* bc0 = (float*)sym_addr(g_bc0);
    float* b01 = (float*)sym_addr(g_b01);
    __nv_bfloat16* wc0h = (__nv_bfloat16*)sym_addr(g_wc0h);
    __nv_bfloat16* wc0l = (__nv_bfloat16*)sym_addr(g_wc0l);
    __nv_bfloat16* w01h = (__nv_bfloat16*)sym_addr(g_w01h);
    __nv_bfloat16* w01l = (__nv_bfloat16*)sym_addr(g_w01l);
    __nv_bfloat16* pwh = (__nv_bfloat16*)sym_addr(g_pwh);
    __nv_bfloat16* pwl = (__nv_bfloat16*)sym_addr(g_pwl);
    __nv_bfloat16* owh = (__nv_bfloat16*)sym_addr(g_owh);
    __nv_bfloat16* owl = (__nv_bfloat16*)sym_addr(g_owl);

    // CSR build
    zero_kernel<<<(NN + 255) / 256, 256>>>();
    hist_kernel<<<(E + 255) / 256, 256>>>(ei, E);
    dinv_kernel<<<(NN + 255) / 256, 256>>>();
    scan1_kernel<<<NB, 1024>>>();
    scan2_kernel<<<1, 64>>>();
    scan3_kernel<<<NB, 1024>>>(E);
    scatter_kernel<<<(E + 255) / 256, 256>>>(ei, et, E);

    // weight prep (writes split bf16 directly)
    wprep1_kernel<<<(2 * 81920 + 255) / 256, 256>>>(ww, wr);
    bprep1_kernel<<<(2 * 640 + 255) / 256, 256>>>(wb, wr);
    wprep2_kernel<<<(81920 + 255) / 256, 256>>>(ow);
    bprep2_kernel<<<(640 + 255) / 256, 256>>>(ob);
    split_kernel<<<(16384 + 255) / 256, 256>>>(pw, pwh, pwl, 16384);
    split_kernel<<<(16384 + 255) / 256, 256>>>(ow + 16384, owh, owl, 16384);
    split_kernel<<<(NN * 128 + 255) / 256, 256>>>(x, xsh, xsl, NN * 128);

    int mtiles = (NN + 127) / 128;

    gemm_bf16<0><<<dim3(1, mtiles), 256>>>(xsh, xsl, pwh, pwl, pb, hbuf, NN, 128, 128, nullptr);
    colstats_kernel<<<512, 128>>>();
    bnrelu_kernel<<<(NN * 128 + 255) / 256, 256>>>(bg, bb);

    // layer 0
    gemm_bf16<1><<<dim3(5, mtiles), 256>>>(hh, hl, wc0h, wc0l, bc0, nullptr, NN, 640, 0, nullptr);
    edge_kernel<<<(NN * 32 + 255) / 256, 256>>>();

    // layer 1 (fused layer0-out)
    gemm_bf16<1><<<dim3(5, mtiles), 256>>>(zh, zl, w01h, w01l, b01, nullptr, NN, 640, 0, nullptr);
    edge_kernel<<<(NN * 32 + 255) / 256, 256>>>();

    // final: out = gelu(z1[idx] @ out_w1 + ob1)
    gemm_bf16<2><<<dim3(1, (NI + 127) / 128), 256>>>(zh, zl, owh, owl, ob + 128, (float*)d_out,
                                                     NI, 128, 128, idx);
}

// round 5
// speedup vs baseline: 2.2322x; 1.0978x over previous
#include <cuda_runtime.h>
#include <cuda_bf16.h>
#include <math.h>

#define NN 48758
#define EMAX 780000
#define NB 48   // ceil(NN/1024)

// ---------------- device scratch ----------------
__device__ __align__(16) float g_h[(size_t)NN * 128];
__device__ __align__(16) __nv_bfloat16 g_hh[(size_t)NN * 128];
__device__ __align__(16) __nv_bfloat16 g_hl[(size_t)NN * 128];
__device__ __align__(16) __nv_bfloat16 g_xsh[(size_t)NN * 128];
__device__ __align__(16) __nv_bfloat16 g_xsl[(size_t)NN * 128];
__device__ __align__(16) __nv_bfloat16 g_zh[(size_t)NN * 128];
__device__ __align__(16) __nv_bfloat16 g_zl[(size_t)NN * 128];
__device__ __align__(16) float    g_xw[(size_t)NN * 128];
__device__ __align__(16) unsigned g_erp[(size_t)NN * 512];  // packed bf16x2 (er, p)
__device__ int   g_off[NN + 1];
__device__ int   g_cur[NN];
__device__ int   g_degsrc[NN];
__device__ int   g_degdst[NN];
__device__ float g_dinv[NN];
__device__ int   g_pk[EMAX];
__device__ float g_nrm[EMAX];
__device__ int   g_bsum[64];
__device__ float g_colsum[128], g_colsq[128];
__device__ float g_wc1[128 * 640];
__device__ float g_bc0[640], g_bc1[640], g_b01[640];
__device__ __nv_bfloat16 g_wc0h[128 * 640], g_wc0l[128 * 640];
__device__ __nv_bfloat16 g_w01h[128 * 640], g_w01l[128 * 640];
__device__ __nv_bfloat16 g_pwh[128 * 128], g_pwl[128 * 128];
__device__ __nv_bfloat16 g_owh[128 * 128], g_owl[128 * 128];

__device__ __forceinline__ float dinvf(int dg) {
    return dg > 0 ? rsqrtf((float)dg) : 0.0f;
}

// ---------------- CSR build ----------------
__global__ void zero_kernel() {
    int i = blockIdx.x * blockDim.x + threadIdx.x;
    if (i < NN) { g_degsrc[i] = 0; g_degdst[i] = 0; }
    if (i < 128) { g_colsum[i] = 0.0f; g_colsq[i] = 0.0f; }
}

__global__ void hist_kernel(const int* __restrict__ ei, int E) {
    int e = blockIdx.x * blockDim.x + threadIdx.x;
    if (e >= E) return;
    atomicAdd(&g_degdst[ei[e]], 1);
    atomicAdd(&g_degsrc[ei[E + e]], 1);
}

// block sums of degdst + dinv table
__global__ void scan1_kernel() {
    __shared__ int sm[1024];
    int tid = threadIdx.x;
    int i = blockIdx.x * 1024 + tid;
    if (i < NN) g_dinv[i] = dinvf(g_degsrc[i]);
    int v = (i < NN) ? g_degdst[i] : 0;
    sm[tid] = v;
    __syncthreads();
    for (int ofs = 512; ofs > 0; ofs >>= 1) {
        if (tid < ofs) sm[tid] += sm[tid + ofs];
        __syncthreads();
    }
    if (tid == 0) g_bsum[blockIdx.x] = sm[0];
}

// full scan (block-local inclusive + inline scan of block sums)
__global__ void scan3_kernel(int E) {
    __shared__ int sm[1024];
    __shared__ int base_s;
    int tid = threadIdx.x;
    int i = blockIdx.x * 1024 + tid;
    int v = (i < NN) ? g_degdst[i] : 0;
    sm[tid] = v;
    if (tid == 0) {
        int b = 0;
        for (int j = 0; j < blockIdx.x; j++) b += g_bsum[j];
        base_s = b;
    }
    __syncthreads();
    for (int ofs = 1; ofs < 1024; ofs <<= 1) {
        int t = (tid >= ofs) ? sm[tid - ofs] : 0;
        __syncthreads();
        sm[tid] += t;
        __syncthreads();
    }
    if (i < NN) {
        int exv = base_s + sm[tid] - v;
        g_off[i] = exv;
        g_cur[i] = exv;
        if (i == NN - 1) g_off[NN] = E;
    }
}

__global__ void scatter_kernel(const int* __restrict__ ei, const int* __restrict__ et, int E) {
    int e = blockIdx.x * blockDim.x + threadIdx.x;
    if (e >= E) return;
    int d = ei[e];
    int s = ei[E + e];
    int slot = atomicAdd(&g_cur[d], 1);
    g_pk[slot] = (s << 2) | et[e];
    g_nrm[slot] = g_dinv[d] * g_dinv[s];
}

// ---------------- consolidated prep ----------------
__device__ __forceinline__ void split_write(__nv_bfloat16* dh, __nv_bfloat16* dl, int i, float f) {
    __nv_bfloat16 h = __float2bfloat16_rn(f);
    dh[i] = h;
    dl[i] = __float2bfloat16_rn(f - __bfloat162float(h));
}

#define XS (NN * 128)
// ranges: [0,XS) x-split | [XS,XS+16384) pw split | [+16384,+32768) ow1 split
//         [+32768,+196608) wprep1 | [+196608,+197888) bprep1
__global__ void prep1_kernel(const float* __restrict__ x, const float* __restrict__ pw,
                             const float* __restrict__ ow, const float* __restrict__ ww,
                             const float* __restrict__ wr, const float* __restrict__ wbv) {
    int i = blockIdx.x * blockDim.x + threadIdx.x;
    if (i < XS) {
        split_write(g_xsh, g_xsl, i, x[i]);
        return;
    }
    int j = i - XS;
    if (j < 16384) { split_write(g_pwh, g_pwl, j, pw[j]); return; }
    j -= 16384;
    if (j < 16384) { split_write(g_owh, g_owl, j, ow[16384 + j]); return; }
    j -= 16384;
    if (j < 163840) {
        // wc[l] = [win_l | win_l @ wrel_l_r]
        int l = j / 81920, rem = j % 81920, k = rem / 640, n = rem % 640;
        float v;
        if (n < 128) {
            v = ww[l * 16384 + k * 128 + n];
        } else {
            int r = (n - 128) >> 7, nn = (n - 128) & 127;
            const float* a = ww + l * 16384 + k * 128;
            const float* b = wr + (size_t)((l * 4 + r) * 128) * 128 + nn;
            float s = 0.f;
            for (int q = 0; q < 128; q++) s += a[q] * b[(size_t)q * 128];
            v = s;
        }
        if (l) g_wc1[rem] = v;
        else   split_write(g_wc0h, g_wc0l, rem, v);
        return;
    }
    j -= 163840;
    if (j < 1280) {
        int l = j / 640, n = j % 640;
        float v;
        if (n < 128) {
            v = wbv[l * 128 + n];
        } else {
            int r = (n - 128) >> 7, nn = (n - 128) & 127;
            const float* a = wbv + l * 128;
            const float* b = wr + (size_t)((l * 4 + r) * 128) * 128 + nn;
            float s = 0.f;
            for (int q = 0; q < 128; q++) s += a[q] * b[(size_t)q * 128];
            v = s;
        }
        (l ? g_bc1 : g_bc0)[n] = v;
    }
}

// W01 = ow0 @ wc1 (split) ; b01 = ob0 @ wc1 + bc1
__global__ void prep2_kernel(const float* __restrict__ ow, const float* __restrict__ obv) {
    int i = blockIdx.x * blockDim.x + threadIdx.x;
    if (i < 81920) {
        int k = i / 640, n = i % 640;
        const float* a = ow + k * 128;
        float s = 0.f;
        for (int q = 0; q < 128; q++) s += a[q] * g_wc1[q * 640 + n];
        split_write(g_w01h, g_w01l, i, s);
        return;
    }
    int n = i - 81920;
    if (n < 640) {
        float s = 0.f;
        for (int q = 0; q < 128; q++) s += obv[q] * g_wc1[q * 640 + n];
        g_b01[n] = s + g_bc1[n];
    }
}

// ---------------- tensor-core GEMM (pre-split bf16, 3xMMA, cp.async pipeline) ----------------
#define LDSM_X4(R, p) asm volatile( \
    "ldmatrix.sync.aligned.m8n8.x4.shared.b16 {%0,%1,%2,%3}, [%4];" \
    : "=r"((R)[0]), "=r"((R)[1]), "=r"((R)[2]), "=r"((R)[3]) : "r"(p))
#define LDSM_X2T(R, p) asm volatile( \
    "ldmatrix.sync.aligned.m8n8.x2.trans.shared.b16 {%0,%1}, [%2];" \
    : "=r"((R)[0]), "=r"((R)[1]) : "r"(p))
#define MMA_BF16(d, a, b) asm volatile( \
    "mma.sync.aligned.m16n8k16.row.col.f32.bf16.bf16.f32 " \
    "{%0,%1,%2,%3},{%4,%5,%6,%7},{%8,%9},{%0,%1,%2,%3};" \
    : "+f"((d)[0]), "+f"((d)[1]), "+f"((d)[2]), "+f"((d)[3]) \
    : "r"((a)[0]), "r"((a)[1]), "r"((a)[2]), "r"((a)[3]), "r"((b)[0]), "r"((b)[1]))

__device__ __forceinline__ void cpa16(void* dst, const void* src, int sz) {
    unsigned d = (unsigned)__cvta_generic_to_shared(dst);
    asm volatile("cp.async.cg.shared.global [%0], [%1], 16, %2;" :: "r"(d), "l"(src), "r"(sz));
}
__device__ __forceinline__ void cpa_commit() { asm volatile("cp.async.commit_group;"); }

__device__ __forceinline__ unsigned packerp(float v) {
    float er = __expf(v);
    float p = v * er;
    __nv_bfloat162 t = __halves2bfloat162(__float2bfloat16_rn(er), __float2bfloat16_rn(p));
    return *reinterpret_cast<unsigned*>(&t);
}

// MODE 0: C = acc + bias (fp32) + fused column stats (atomicAdd into g_colsum/g_colsq)
// MODE 1: bn==0 -> g_xw fp32 ; bn>0 -> g_erp packed(exp(v), v*exp(v))
// MODE 2: C = gelu(acc + bias), rows via ridx gather on A
template <int MODE>
__global__ __launch_bounds__(256, 2)
void gemm_bf16(const __nv_bfloat16* __restrict__ Ah, const __nv_bfloat16* __restrict__ Al,
               const __nv_bfloat16* __restrict__ Bh, const __nv_bfloat16* __restrict__ Bl,
               const float* __restrict__ bias, float* __restrict__ C,
               int M, int ldb, int ldc, const int* __restrict__ ridx) {
    __shared__ __align__(16) __nv_bfloat16 Ahs[2][128][40];
    __shared__ __align__(16) __nv_bfloat16 Als[2][128][40];
    __shared__ __align__(16) __nv_bfloat16 Bhs[2][32][136];
    __shared__ __align__(16) __nv_bfloat16 Bls[2][32][136];

    int tid = threadIdx.x, lane = tid & 31, warp = tid >> 5;
    int wm = warp >> 2, wn = warp & 3;
    int bm = blockIdx.y * 128, bn = blockIdx.x * 128;

    float acc[4][4][4];
#pragma unroll
    for (int a = 0; a < 4; a++)
#pragma unroll
        for (int b = 0; b < 4; b++)
#pragma unroll
            for (int c = 0; c < 4; c++) acc[a][b][c] = 0.0f;

    int arr[2], asz[2];
#pragma unroll
    for (int i = 0; i < 2; i++) {
        int row = (tid + i * 256) >> 2;
        int grow = bm + row;
        bool ok = grow < M;
        arr[i] = ok ? (ridx ? ridx[grow] : grow) : 0;
        asz[i] = ok ? 16 : 0;
    }

#define LOAD_CHUNK(st, k0)                                                        \
    {                                                                             \
        _Pragma("unroll")                                                         \
        for (int i = 0; i < 2; i++) {                                             \
            int vec = tid + i * 256;                                              \
            int row = vec >> 2;                                                   \
            int c8 = (vec & 3) * 8;                                               \
            size_t go = (size_t)arr[i] * 128 + (k0) + c8;                         \
            cpa16(&Ahs[st][row][c8], Ah + go, asz[i]);                            \
            cpa16(&Als[st][row][c8], Al + go, asz[i]);                            \
        }                                                                         \
        _Pragma("unroll")                                                         \
        for (int i = 0; i < 2; i++) {                                             \
            int vec = tid + i * 256;                                              \
            int row = vec >> 4;                                                   \
            int c8 = (vec & 15) * 8;                                              \
            size_t go = (size_t)((k0) + row) * ldb + bn + c8;                     \
            cpa16(&Bhs[st][row][c8], Bh + go, 16);                                \
            cpa16(&Bls[st][row][c8], Bl + go, 16);                                \
        }                                                                         \
        cpa_commit();                                                             \
    }

    LOAD_CHUNK(0, 0)
    LOAD_CHUNK(1, 32)

#pragma unroll
    for (int k0i = 0; k0i < 4; k0i++) {
        int st = k0i & 1;
        if (k0i < 3) asm volatile("cp.async.wait_group 1;");
        else         asm volatile("cp.async.wait_group 0;");
        __syncthreads();

#pragma unroll
        for (int k16 = 0; k16 < 32; k16 += 16) {
            unsigned af[4][4], bhf[4][2], blf[4][2];
            int arow = wm * 64 + (lane & 15);
            int acol = k16 + ((lane >> 4) << 3);
#pragma unroll
            for (int mt = 0; mt < 4; mt++) {
                unsigned p = (unsigned)__cvta_generic_to_shared(&Ahs[st][arow + mt * 16][acol]);
                LDSM_X4(af[mt], p);
            }
            int brow = k16 + (lane & 15);
#pragma unroll
            for (int nt = 0; nt < 4; nt++) {
                int n0 = wn * 32 + nt * 8;
                unsigned ph = (unsigned)__cvta_generic_to_shared(&Bhs[st][brow][n0]);
                unsigned pl = (unsigned)__cvta_generic_to_shared(&Bls[st][brow][n0]);
                LDSM_X2T(bhf[nt], ph);
                LDSM_X2T(blf[nt], pl);
            }
#pragma unroll
            for (int mt = 0; mt < 4; mt++)
#pragma unroll
                for (int nt = 0; nt < 4; nt++) MMA_BF16(acc[mt][nt], af[mt], bhf[nt]);
#pragma unroll
            for (int mt = 0; mt < 4; mt++)
#pragma unroll
                for (int nt = 0; nt < 4; nt++) MMA_BF16(acc[mt][nt], af[mt], blf[nt]);
#pragma unroll
            for (int mt = 0; mt < 4; mt++) {
                unsigned p = (unsigned)__cvta_generic_to_shared(&Als[st][arow + mt * 16][acol]);
                LDSM_X4(af[mt], p);
            }
#pragma unroll
            for (int mt = 0; mt < 4; mt++)
#pragma unroll
                for (int nt = 0; nt < 4; nt++) MMA_BF16(acc[mt][nt], af[mt], bhf[nt]);
        }
        __syncthreads();
        if (k0i < 2) LOAD_CHUNK(st, (k0i + 2) * 32)
    }

    int r_base = bm + wm * 64;
#pragma unroll
    for (int nt = 0; nt < 4; nt++) {
        int cl = wn * 32 + nt * 8 + ((lane & 3) << 1);
        int cg = bn + cl;
        float2 bv = *(const float2*)(bias + cg);
        float cs0 = 0.f, cs1 = 0.f, cq0 = 0.f, cq1 = 0.f;
#pragma unroll
        for (int mt = 0; mt < 4; mt++) {
            int r0 = r_base + mt * 16 + (lane >> 2);
            int r1 = r0 + 8;
            float v00 = acc[mt][nt][0] + bv.x, v01 = acc[mt][nt][1] + bv.y;
            float v10 = acc[mt][nt][2] + bv.x, v11 = acc[mt][nt][3] + bv.y;
            if (MODE == 0) {
                if (r0 < M) {
                    *(float2*)(C + (size_t)r0 * ldc + cg) = make_float2(v00, v01);
                    cs0 += v00; cs1 += v01; cq0 += v00 * v00; cq1 += v01 * v01;
                }
                if (r1 < M) {
                    *(float2*)(C + (size_t)r1 * ldc + cg) = make_float2(v10, v11);
                    cs0 += v10; cs1 += v11; cq0 += v10 * v10; cq1 += v11 * v11;
                }
            } else if (MODE == 1) {
                if (bn == 0) {
                    if (r0 < M) *(float2*)(g_xw + ((size_t)r0 << 7) + cl) = make_float2(v00, v01);
                    if (r1 < M) *(float2*)(g_xw + ((size_t)r1 << 7) + cl) = make_float2(v10, v11);
                } else {
                    int yc = cg - 128;
                    if (r0 < M) {
                        uint2 u = make_uint2(packerp(v00), packerp(v01));
                        *(uint2*)(g_erp + ((size_t)r0 << 9) + yc) = u;
                    }
                    if (r1 < M) {
                        uint2 u = make_uint2(packerp(v10), packerp(v11));
                        *(uint2*)(g_erp + ((size_t)r1 << 9) + yc) = u;
                    }
                }
            } else {
                if (r0 < M) {
                    float a = 0.5f * v00 * (1.0f + erff(v00 * 0.70710678118654752f));
                    float b = 0.5f * v01 * (1.0f + erff(v01 * 0.70710678118654752f));
                    *(float2*)(C + (size_t)r0 * ldc + cg) = make_float2(a, b);
                }
                if (r1 < M) {
                    float a = 0.5f * v10 * (1.0f + erff(v10 * 0.70710678118654752f));
                    float b = 0.5f * v11 * (1.0f + erff(v11 * 0.70710678118654752f));
                    *(float2*)(C + (size_t)r1 * ldc + cg) = make_float2(a, b);
                }
            }
        }
        if (MODE == 0) {
            // reduce across the 8 lanes covering rows (lane>>2) for the same columns
#pragma unroll
            for (int ofs = 16; ofs >= 4; ofs >>= 1) {
                cs0 += __shfl_down_sync(0xffffffffu, cs0, ofs);
                cs1 += __shfl_down_sync(0xffffffffu, cs1, ofs);
                cq0 += __shfl_down_sync(0xffffffffu, cq0, ofs);
                cq1 += __shfl_down_sync(0xffffffffu, cq1, ofs);
            }
            if ((lane >> 2) == 0) {
                atomicAdd(&g_colsum[cg], cs0);
                atomicAdd(&g_colsum[cg + 1], cs1);
                atomicAdd(&g_colsq[cg], cq0);
                atomicAdd(&g_colsq[cg + 1], cq1);
            }
        }
    }
#undef LOAD_CHUNK
}

// ---------------- BatchNorm apply + relu + split ----------------
__global__ void bnrelu_kernel(const float* __restrict__ bg, const float* __restrict__ bb) {
    int i = blockIdx.x * blockDim.x + threadIdx.x;
    if (i >= NN * 128) return;
    int c = i & 127;
    float invn = 1.0f / (float)NN;
    float mu = g_colsum[c] * invn;
    float var = g_colsq[c] * invn - mu * mu;
    float v = (g_h[i] - mu) * rsqrtf(var + 1e-5f) * bg[c] + bb[c];
    v = fmaxf(v, 0.f);
    __nv_bfloat16 h = __float2bfloat16_rn(v);
    g_hh[i] = h;
    g_hl[i] = __float2bfloat16_rn(v - __bfloat162float(h));
}

// ---------------- edge stage ----------------
__global__ void edge_kernel() {
    int w = (blockIdx.x * blockDim.x + threadIdx.x) >> 5;
    if (w >= NN) return;
    int lane = threadIdx.x & 31;
    int c = lane << 2;
    int s0 = g_off[w], s1 = g_off[w + 1];
    float4 z = make_float4(0.f, 0.f, 0.f, 0.f);
    if (s0 < s1) {
        float gx = 0.f, gy = 0.f, gz = 0.f, gw = 0.f;
        float d0 = 0.f, d1 = 0.f, d2 = 0.f, d3 = 0.f;
        float n0 = 0.f, n1 = 0.f, n2 = 0.f, n3 = 0.f;
#pragma unroll 2
        for (int e = s0; e < s1; e++) {
            int pk = __ldg(&g_pk[e]);
            float wn = __ldg(&g_nrm[e]);
            int s = pk >> 2, t = pk & 3;
            float4 xj = *(const float4*)(g_xw + ((size_t)s << 7) + c);
            uint4 ep = *(const uint4*)(g_erp + ((size_t)s << 9) + (t << 7) + c);
            float2 a0 = __bfloat1622float2(*(__nv_bfloat162*)&ep.x);
            float2 a1 = __bfloat1622float2(*(__nv_bfloat162*)&ep.y);
            float2 a2 = __bfloat1622float2(*(__nv_bfloat162*)&ep.z);
            float2 a3 = __bfloat1622float2(*(__nv_bfloat162*)&ep.w);
            d0 += a0.x; n0 += a0.y;
            d1 += a1.x; n1 += a1.y;
            d2 += a2.x; n2 += a2.y;
            d3 += a3.x; n3 += a3.y;
            gx += xj.x * wn; gy += xj.y * wn; gz += xj.z * wn; gw += xj.w * wn;
        }
        z.x = gx + 0.1f * fmaxf(n0 / d0, 0.f);
        z.y = gy + 0.1f * fmaxf(n1 / d1, 0.f);
        z.z = gz + 0.1f * fmaxf(n2 / d2, 0.f);
        z.w = gw + 0.1f * fmaxf(n3 / d3, 0.f);
    }
    __nv_bfloat16 h0 = __float2bfloat16_rn(z.x), h1 = __float2bfloat16_rn(z.y);
    __nv_bfloat16 h2 = __float2bfloat16_rn(z.z), h3 = __float2bfloat16_rn(z.w);
    __nv_bfloat16 l0 = __float2bfloat16_rn(z.x - __bfloat162float(h0));
    __nv_bfloat16 l1 = __float2bfloat16_rn(z.y - __bfloat162float(h1));
    __nv_bfloat16 l2 = __float2bfloat16_rn(z.z - __bfloat162float(h2));
    __nv_bfloat16 l3 = __float2bfloat16_rn(z.w - __bfloat162float(h3));
    __nv_bfloat162 ph0 = __halves2bfloat162(h0, h1), ph1 = __halves2bfloat162(h2, h3);
    __nv_bfloat162 pl0 = __halves2bfloat162(l0, l1), pl1 = __halves2bfloat162(l2, l3);
    size_t o = ((size_t)w << 7) + c;
    *(uint2*)(g_zh + o) = make_uint2(*(unsigned*)&ph0, *(unsigned*)&ph1);
    *(uint2*)(g_zl + o) = make_uint2(*(unsigned*)&pl0, *(unsigned*)&pl1);
}

// ---------------- host launcher ----------------
static void* sym_addr(const void* sym) {
    void* p = nullptr;
    cudaGetSymbolAddress(&p, sym);
    return p;
}

extern "C" void kernel_launch(void* const* d_in, const int* in_sizes, int n_in,
                              void* d_out, int out_size) {
    int ix, iei, iidx, iet, ipw, ipb, ibg, ibb, iww, iwb, iwr, iow, iob;
    if (in_sizes[1] > 1000000) {
        ix = 0; iei = 1; iidx = 2; iet = 3; ipw = 5; ipb = 6; ibg = 7; ibb = 8;
        iww = 9; iwb = 10; iwr = 11; iow = 12; iob = 13;
    } else {
        ix = 0; ipw = 2; ipb = 3; ibg = 4; ibb = 5; iww = 6; iwb = 7;
        iwr = 8; iow = 9; iob = 10; iei = 11; iet = 12; iidx = 13;
    }

    const float* x   = (const float*)d_in[ix];
    const int*   ei  = (const int*)d_in[iei];
    const int*   et  = (const int*)d_in[iet];
    const int*   idx = (const int*)d_in[iidx];
    const float* pw  = (const float*)d_in[ipw];
    const float* pb  = (const float*)d_in[ipb];
    const float* bg  = (const float*)d_in[ibg];
    const float* bb  = (const float*)d_in[ibb];
    const float* ww  = (const float*)d_in[iww];
    const float* wb  = (const float*)d_in[iwb];
    const float* wr  = (const float*)d_in[iwr];
    const float* ow  = (const float*)d_in[iow];
    const float* ob  = (const float*)d_in[iob];

    int E  = in_sizes[iei] / 2;
    int NI = out_size / 128;

    float* hbuf  = (float*)sym_addr(g_h);
    __nv_bfloat16* hh  = (__nv_bfloat16*)sym_addr(g_hh);
    __nv_bfloat16* hl  = (__nv_bfloat16*)sym_addr(g_hl);
    __nv_bfloat16* xsh = (__nv_bfloat16*)sym_addr(g_xsh);
    __nv_bfloat16* xsl = (__nv_bfloat16*)sym_addr(g_xsl);
    __nv_bfloat16* zh  = (__nv_bfloat16*)sym_addr(g_zh);
    __nv_bfloat16* zl  = (__nv_bfloat16*)sym_addr(g_zl);
    float* bc0 = (float*)sym_addr(g_bc0);
    float* b01 = (float*)sym_addr(g_b01);
    __nv_bfloat16* wc0h = (__nv_bfloat16*)sym_addr(g_wc0h);
    __nv_bfloat16* wc0l = (__nv_bfloat16*)sym_addr(g_wc0l);
    __nv_bfloat16* w01h = (__nv_bfloat16*)sym_addr(g_w01h);
    __nv_bfloat16* w01l = (__nv_bfloat16*)sym_addr(g_w01l);
    __nv_bfloat16* pwh = (__nv_bfloat16*)sym_addr(g_pwh);
    __nv_bfloat16* pwl = (__nv_bfloat16*)sym_addr(g_pwl);
    __nv_bfloat16* owh = (__nv_bfloat16*)sym_addr(g_owh);
    __nv_bfloat16* owl = (__nv_bfloat16*)sym_addr(g_owl);

    // CSR build (4 launches + scatter)
    zero_kernel<<<(NN + 255) / 256, 256>>>();
    hist_kernel<<<(E + 255) / 256, 256>>>(ei, E);
    scan1_kernel<<<NB, 1024>>>();
    scan3_kernel<<<NB, 1024>>>(E);
    scatter_kernel<<<(E + 255) / 256, 256>>>(ei, et, E);

    // consolidated prep (2 launches)
    int prep1_total = XS + 16384 + 16384 + 163840 + 1280;
    prep1_kernel<<<(prep1_total + 255) / 256, 256>>>(x, pw, ow, ww, wr, wb);
    prep2_kernel<<<(81920 + 640 + 255) / 256, 256>>>(ow, ob);

    int mtiles = (NN + 127) / 128;

    // projection (+ fused column stats) + BN/relu/split
    gemm_bf16<0><<<dim3(1, mtiles), 256>>>(xsh, xsl, pwh, pwl, pb, hbuf, NN, 128, 128, nullptr);
    bnrelu_kernel<<<(NN * 128 + 255) / 256, 256>>>(bg, bb);

    // layer 0
    gemm_bf16<1><<<dim3(5, mtiles), 256>>>(hh, hl, wc0h, wc0l, bc0, nullptr, NN, 640, 0, nullptr);
    edge_kernel<<<(NN * 32 + 255) / 256, 256>>>();

    // layer 1 (fused layer0-out)
    gemm_bf16<1><<<dim3(5, mtiles), 256>>>(zh, zl, w01h, w01l, b01, nullptr, NN, 640, 0, nullptr);
    edge_kernel<<<(NN * 32 + 255) / 256, 256>>>();

    // final: out = gelu(z1[idx] @ out_w1 + ob1)
    gemm_bf16<2><<<dim3(1, (NI + 127) / 128), 256>>>(zh, zl, owh, owl, ob + 128, (float*)d_out,
                                                     NI, 128, 128, idx);
}

// round 6
// speedup vs baseline: 2.3428x; 1.0496x over previous
#include <cuda_runtime.h>
#include <cuda_bf16.h>
#include <math.h>

#define NN 48758
#define EMAX 780000
#define NB 48   // ceil(NN/1024)

// ---------------- device scratch ----------------
__device__ __align__(16) float g_h[(size_t)NN * 128];
__device__ __align__(16) __nv_bfloat16 g_hh[(size_t)NN * 128];
__device__ __align__(16) __nv_bfloat16 g_hl[(size_t)NN * 128];
__device__ __align__(16) __nv_bfloat16 g_xsh[(size_t)NN * 128];
__device__ __align__(16) __nv_bfloat16 g_xsl[(size_t)NN * 128];
__device__ __align__(16) __nv_bfloat16 g_zh[(size_t)NN * 128];
__device__ __align__(16) __nv_bfloat16 g_zl[(size_t)NN * 128];
__device__ __align__(16) float    g_xw[(size_t)NN * 128];
__device__ __align__(16) unsigned g_erp[(size_t)NN * 512];  // packed bf16x2 (er, p)
__device__ int   g_off[NN + 1];
__device__ int   g_cur[NN];
__device__ int   g_degsrc[NN];
__device__ int   g_degdst[NN];
__device__ float g_dinv[NN];
__device__ int   g_pk[EMAX];
__device__ float g_nrm[EMAX];
__device__ int   g_bsum[64];
__device__ float g_colsum[128], g_colsq[128];
__device__ float g_wc1[128 * 640];
__device__ float g_bc0[640], g_bc1[640], g_b01[640];
__device__ __nv_bfloat16 g_wc0h[128 * 640], g_wc0l[128 * 640];
__device__ __nv_bfloat16 g_w01h[128 * 640], g_w01l[128 * 640];
__device__ __nv_bfloat16 g_pwh[128 * 128], g_pwl[128 * 128];
__device__ __nv_bfloat16 g_owh[128 * 128], g_owl[128 * 128];

__device__ __forceinline__ float dinvf(int dg) {
    return dg > 0 ? rsqrtf((float)dg) : 0.0f;
}

// ---------------- CSR build ----------------
__global__ void zero_kernel() {
    int i = blockIdx.x * blockDim.x + threadIdx.x;
    if (i < NN) { g_degsrc[i] = 0; g_degdst[i] = 0; }
    if (i < 128) { g_colsum[i] = 0.0f; g_colsq[i] = 0.0f; }
}

__global__ void hist_kernel(const int* __restrict__ ei, int E) {
    int e = blockIdx.x * blockDim.x + threadIdx.x;
    if (e >= E) return;
    atomicAdd(&g_degdst[ei[e]], 1);
    atomicAdd(&g_degsrc[ei[E + e]], 1);
}

// block sums of degdst + dinv table
__global__ void scan1_kernel() {
    __shared__ int sm[1024];
    int tid = threadIdx.x;
    int i = blockIdx.x * 1024 + tid;
    if (i < NN) g_dinv[i] = dinvf(g_degsrc[i]);
    int v = (i < NN) ? g_degdst[i] : 0;
    sm[tid] = v;
    __syncthreads();
    for (int ofs = 512; ofs > 0; ofs >>= 1) {
        if (tid < ofs) sm[tid] += sm[tid + ofs];
        __syncthreads();
    }
    if (tid == 0) g_bsum[blockIdx.x] = sm[0];
}

// full scan (block-local inclusive + inline scan of block sums)
__global__ void scan3_kernel(int E) {
    __shared__ int sm[1024];
    __shared__ int base_s;
    int tid = threadIdx.x;
    int i = blockIdx.x * 1024 + tid;
    int v = (i < NN) ? g_degdst[i] : 0;
    sm[tid] = v;
    if (tid == 0) {
        int b = 0;
        for (int j = 0; j < blockIdx.x; j++) b += g_bsum[j];
        base_s = b;
    }
    __syncthreads();
    for (int ofs = 1; ofs < 1024; ofs <<= 1) {
        int t = (tid >= ofs) ? sm[tid - ofs] : 0;
        __syncthreads();
        sm[tid] += t;
        __syncthreads();
    }
    if (i < NN) {
        int exv = base_s + sm[tid] - v;
        g_off[i] = exv;
        g_cur[i] = exv;
        if (i == NN - 1) g_off[NN] = E;
    }
}

__global__ void scatter_kernel(const int* __restrict__ ei, const int* __restrict__ et, int E) {
    int e = blockIdx.x * blockDim.x + threadIdx.x;
    if (e >= E) return;
    int d = ei[e];
    int s = ei[E + e];
    int slot = atomicAdd(&g_cur[d], 1);
    g_pk[slot] = (s << 2) | et[e];
    g_nrm[slot] = g_dinv[d] * g_dinv[s];
}

// ---------------- consolidated prep ----------------
__device__ __forceinline__ void split_write(__nv_bfloat16* dh, __nv_bfloat16* dl, int i, float f) {
    __nv_bfloat16 h = __float2bfloat16_rn(f);
    dh[i] = h;
    dl[i] = __float2bfloat16_rn(f - __bfloat162float(h));
}

#define XS (NN * 128)
// ranges: [0,XS) x-split | [XS,XS+16384) pw split | [+16384,+32768) ow1 split
//         [+32768,+196608) wprep1 | [+196608,+197888) bprep1
__global__ void prep1_kernel(const float* __restrict__ x, const float* __restrict__ pw,
                             const float* __restrict__ ow, const float* __restrict__ ww,
                             const float* __restrict__ wr, const float* __restrict__ wbv) {
    int i = blockIdx.x * blockDim.x + threadIdx.x;
    if (i < XS) {
        split_write(g_xsh, g_xsl, i, x[i]);
        return;
    }
    int j = i - XS;
    if (j < 16384) { split_write(g_pwh, g_pwl, j, pw[j]); return; }
    j -= 16384;
    if (j < 16384) { split_write(g_owh, g_owl, j, ow[16384 + j]); return; }
    j -= 16384;
    if (j < 163840) {
        // wc[l] = [win_l | win_l @ wrel_l_r]
        int l = j / 81920, rem = j % 81920, k = rem / 640, n = rem % 640;
        float v;
        if (n < 128) {
            v = ww[l * 16384 + k * 128 + n];
        } else {
            int r = (n - 128) >> 7, nn = (n - 128) & 127;
            const float* a = ww + l * 16384 + k * 128;
            const float* b = wr + (size_t)((l * 4 + r) * 128) * 128 + nn;
            float s = 0.f;
            for (int q = 0; q < 128; q++) s += a[q] * b[(size_t)q * 128];
            v = s;
        }
        if (l) g_wc1[rem] = v;
        else   split_write(g_wc0h, g_wc0l, rem, v);
        return;
    }
    j -= 163840;
    if (j < 1280) {
        int l = j / 640, n = j % 640;
        float v;
        if (n < 128) {
            v = wbv[l * 128 + n];
        } else {
            int r = (n - 128) >> 7, nn = (n - 128) & 127;
            const float* a = wbv + l * 128;
            const float* b = wr + (size_t)((l * 4 + r) * 128) * 128 + nn;
            float s = 0.f;
            for (int q = 0; q < 128; q++) s += a[q] * b[(size_t)q * 128];
            v = s;
        }
        (l ? g_bc1 : g_bc0)[n] = v;
    }
}

// W01 = ow0 @ wc1 (split) ; b01 = ob0 @ wc1 + bc1
__global__ void prep2_kernel(const float* __restrict__ ow, const float* __restrict__ obv) {
    int i = blockIdx.x * blockDim.x + threadIdx.x;
    if (i < 81920) {
        int k = i / 640, n = i % 640;
        const float* a = ow + k * 128;
        float s = 0.f;
        for (int q = 0; q < 128; q++) s += a[q] * g_wc1[q * 640 + n];
        split_write(g_w01h, g_w01l, i, s);
        return;
    }
    int n = i - 81920;
    if (n < 640) {
        float s = 0.f;
        for (int q = 0; q < 128; q++) s += obv[q] * g_wc1[q * 640 + n];
        g_b01[n] = s + g_bc1[n];
    }
}

// ---------------- tensor-core GEMM (pre-split bf16, 3xMMA, cp.async pipeline) ----------------
#define LDSM_X4(R, p) asm volatile( \
    "ldmatrix.sync.aligned.m8n8.x4.shared.b16 {%0,%1,%2,%3}, [%4];" \
    : "=r"((R)[0]), "=r"((R)[1]), "=r"((R)[2]), "=r"((R)[3]) : "r"(p))
#define LDSM_X2T(R, p) asm volatile( \
    "ldmatrix.sync.aligned.m8n8.x2.trans.shared.b16 {%0,%1}, [%2];" \
    : "=r"((R)[0]), "=r"((R)[1]) : "r"(p))
#define MMA_BF16(d, a, b) asm volatile( \
    "mma.sync.aligned.m16n8k16.row.col.f32.bf16.bf16.f32 " \
    "{%0,%1,%2,%3},{%4,%5,%6,%7},{%8,%9},{%0,%1,%2,%3};" \
    : "+f"((d)[0]), "+f"((d)[1]), "+f"((d)[2]), "+f"((d)[3]) \
    : "r"((a)[0]), "r"((a)[1]), "r"((a)[2]), "r"((a)[3]), "r"((b)[0]), "r"((b)[1]))

__device__ __forceinline__ void cpa16(void* dst, const void* src, int sz) {
    unsigned d = (unsigned)__cvta_generic_to_shared(dst);
    asm volatile("cp.async.cg.shared.global [%0], [%1], 16, %2;" :: "r"(d), "l"(src), "r"(sz));
}
__device__ __forceinline__ void cpa_commit() { asm volatile("cp.async.commit_group;"); }

__device__ __forceinline__ unsigned packerp(float v) {
    float er = __expf(v);
    float p = v * er;
    __nv_bfloat162 t = __halves2bfloat162(__float2bfloat16_rn(er), __float2bfloat16_rn(p));
    return *reinterpret_cast<unsigned*>(&t);
}

// MODE 0: C = acc + bias (fp32) + fused column stats
// MODE 1: bn==0 -> g_xw fp32 ; bn>0 -> g_erp packed(exp(v), v*exp(v))
// MODE 2: C = gelu(acc + bias), rows via ridx gather on A
template <int MODE>
__global__ __launch_bounds__(256, 2)
void gemm_bf16(const __nv_bfloat16* __restrict__ Ah, const __nv_bfloat16* __restrict__ Al,
               const __nv_bfloat16* __restrict__ Bh, const __nv_bfloat16* __restrict__ Bl,
               const float* __restrict__ bias, float* __restrict__ C,
               int M, int ldb, int ldc, const int* __restrict__ ridx) {
    __shared__ __align__(16) __nv_bfloat16 Ahs[2][128][40];
    __shared__ __align__(16) __nv_bfloat16 Als[2][128][40];
    __shared__ __align__(16) __nv_bfloat16 Bhs[2][32][136];
    __shared__ __align__(16) __nv_bfloat16 Bls[2][32][136];

    int tid = threadIdx.x, lane = tid & 31, warp = tid >> 5;
    int wm = warp >> 2, wn = warp & 3;
    int bm = blockIdx.y * 128, bn = blockIdx.x * 128;

    float acc[4][4][4];
#pragma unroll
    for (int a = 0; a < 4; a++)
#pragma unroll
        for (int b = 0; b < 4; b++)
#pragma unroll
            for (int c = 0; c < 4; c++) acc[a][b][c] = 0.0f;

    int arr[2], asz[2];
#pragma unroll
    for (int i = 0; i < 2; i++) {
        int row = (tid + i * 256) >> 2;
        int grow = bm + row;
        bool ok = grow < M;
        arr[i] = ok ? (ridx ? ridx[grow] : grow) : 0;
        asz[i] = ok ? 16 : 0;
    }

#define LOAD_CHUNK(st, k0)                                                        \
    {                                                                             \
        _Pragma("unroll")                                                         \
        for (int i = 0; i < 2; i++) {                                             \
            int vec = tid + i * 256;                                              \
            int row = vec >> 2;                                                   \
            int c8 = (vec & 3) * 8;                                               \
            size_t go = (size_t)arr[i] * 128 + (k0) + c8;                         \
            cpa16(&Ahs[st][row][c8], Ah + go, asz[i]);                            \
            cpa16(&Als[st][row][c8], Al + go, asz[i]);                            \
        }                                                                         \
        _Pragma("unroll")                                                         \
        for (int i = 0; i < 2; i++) {                                             \
            int vec = tid + i * 256;                                              \
            int row = vec >> 4;                                                   \
            int c8 = (vec & 15) * 8;                                              \
            size_t go = (size_t)((k0) + row) * ldb + bn + c8;                     \
            cpa16(&Bhs[st][row][c8], Bh + go, 16);                                \
            cpa16(&Bls[st][row][c8], Bl + go, 16);                                \
        }                                                                         \
        cpa_commit();                                                             \
    }

    LOAD_CHUNK(0, 0)
    LOAD_CHUNK(1, 32)

#pragma unroll
    for (int k0i = 0; k0i < 4; k0i++) {
        int st = k0i & 1;
        if (k0i < 3) asm volatile("cp.async.wait_group 1;");
        else         asm volatile("cp.async.wait_group 0;");
        __syncthreads();

#pragma unroll
        for (int k16 = 0; k16 < 32; k16 += 16) {
            unsigned af[4][4], bhf[4][2], blf[4][2];
            int arow = wm * 64 + (lane & 15);
            int acol = k16 + ((lane >> 4) << 3);
#pragma unroll
            for (int mt = 0; mt < 4; mt++) {
                unsigned p = (unsigned)__cvta_generic_to_shared(&Ahs[st][arow + mt * 16][acol]);
                LDSM_X4(af[mt], p);
            }
            int brow = k16 + (lane & 15);
#pragma unroll
            for (int nt = 0; nt < 4; nt++) {
                int n0 = wn * 32 + nt * 8;
                unsigned ph = (unsigned)__cvta_generic_to_shared(&Bhs[st][brow][n0]);
                unsigned pl = (unsigned)__cvta_generic_to_shared(&Bls[st][brow][n0]);
                LDSM_X2T(bhf[nt], ph);
                LDSM_X2T(blf[nt], pl);
            }
#pragma unroll
            for (int mt = 0; mt < 4; mt++)
#pragma unroll
                for (int nt = 0; nt < 4; nt++) MMA_BF16(acc[mt][nt], af[mt], bhf[nt]);
#pragma unroll
            for (int mt = 0; mt < 4; mt++)
#pragma unroll
                for (int nt = 0; nt < 4; nt++) MMA_BF16(acc[mt][nt], af[mt], blf[nt]);
#pragma unroll
            for (int mt = 0; mt < 4; mt++) {
                unsigned p = (unsigned)__cvta_generic_to_shared(&Als[st][arow + mt * 16][acol]);
                LDSM_X4(af[mt], p);
            }
#pragma unroll
            for (int mt = 0; mt < 4; mt++)
#pragma unroll
                for (int nt = 0; nt < 4; nt++) MMA_BF16(acc[mt][nt], af[mt], bhf[nt]);
        }
        __syncthreads();
        if (k0i < 2) LOAD_CHUNK(st, (k0i + 2) * 32)
    }

    int r_base = bm + wm * 64;
#pragma unroll
    for (int nt = 0; nt < 4; nt++) {
        int cl = wn * 32 + nt * 8 + ((lane & 3) << 1);
        int cg = bn + cl;
        float2 bv = *(const float2*)(bias + cg);
        float cs0 = 0.f, cs1 = 0.f, cq0 = 0.f, cq1 = 0.f;
#pragma unroll
        for (int mt = 0; mt < 4; mt++) {
            int r0 = r_base + mt * 16 + (lane >> 2);
            int r1 = r0 + 8;
            float v00 = acc[mt][nt][0] + bv.x, v01 = acc[mt][nt][1] + bv.y;
            float v10 = acc[mt][nt][2] + bv.x, v11 = acc[mt][nt][3] + bv.y;
            if (MODE == 0) {
                if (r0 < M) {
                    *(float2*)(C + (size_t)r0 * ldc + cg) = make_float2(v00, v01);
                    cs0 += v00; cs1 += v01; cq0 += v00 * v00; cq1 += v01 * v01;
                }
                if (r1 < M) {
                    *(float2*)(C + (size_t)r1 * ldc + cg) = make_float2(v10, v11);
                    cs0 += v10; cs1 += v11; cq0 += v10 * v10; cq1 += v11 * v11;
                }
            } else if (MODE == 1) {
                if (bn == 0) {
                    if (r0 < M) *(float2*)(g_xw + ((size_t)r0 << 7) + cl) = make_float2(v00, v01);
                    if (r1 < M) *(float2*)(g_xw + ((size_t)r1 << 7) + cl) = make_float2(v10, v11);
                } else {
                    int yc = cg - 128;
                    if (r0 < M) {
                        uint2 u = make_uint2(packerp(v00), packerp(v01));
                        *(uint2*)(g_erp + ((size_t)r0 << 9) + yc) = u;
                    }
                    if (r1 < M) {
                        uint2 u = make_uint2(packerp(v10), packerp(v11));
                        *(uint2*)(g_erp + ((size_t)r1 << 9) + yc) = u;
                    }
                }
            } else {
                if (r0 < M) {
                    float a = 0.5f * v00 * (1.0f + erff(v00 * 0.70710678118654752f));
                    float b = 0.5f * v01 * (1.0f + erff(v01 * 0.70710678118654752f));
                    *(float2*)(C + (size_t)r0 * ldc + cg) = make_float2(a, b);
                }
                if (r1 < M) {
                    float a = 0.5f * v10 * (1.0f + erff(v10 * 0.70710678118654752f));
                    float b = 0.5f * v11 * (1.0f + erff(v11 * 0.70710678118654752f));
                    *(float2*)(C + (size_t)r1 * ldc + cg) = make_float2(a, b);
                }
            }
        }
        if (MODE == 0) {
#pragma unroll
            for (int ofs = 16; ofs >= 4; ofs >>= 1) {
                cs0 += __shfl_down_sync(0xffffffffu, cs0, ofs);
                cs1 += __shfl_down_sync(0xffffffffu, cs1, ofs);
                cq0 += __shfl_down_sync(0xffffffffu, cq0, ofs);
                cq1 += __shfl_down_sync(0xffffffffu, cq1, ofs);
            }
            if ((lane >> 2) == 0) {
                atomicAdd(&g_colsum[cg], cs0);
                atomicAdd(&g_colsum[cg + 1], cs1);
                atomicAdd(&g_colsq[cg], cq0);
                atomicAdd(&g_colsq[cg + 1], cq1);
            }
        }
    }
#undef LOAD_CHUNK
}

// ---------------- BatchNorm apply + relu + split ----------------
__global__ void bnrelu_kernel(const float* __restrict__ bg, const float* __restrict__ bb) {
    int i = blockIdx.x * blockDim.x + threadIdx.x;
    if (i >= NN * 128) return;
    int c = i & 127;
    float invn = 1.0f / (float)NN;
    float mu = g_colsum[c] * invn;
    float var = g_colsq[c] * invn - mu * mu;
    float v = (g_h[i] - mu) * rsqrtf(var + 1e-5f) * bg[c] + bb[c];
    v = fmaxf(v, 0.f);
    __nv_bfloat16 h = __float2bfloat16_rn(v);
    g_hh[i] = h;
    g_hl[i] = __float2bfloat16_rn(v - __bfloat162float(h));
}

// ---------------- edge stage ----------------
__global__ void edge_kernel() {
    int w = (blockIdx.x * blockDim.x + threadIdx.x) >> 5;
    if (w >= NN) return;
    int lane = threadIdx.x & 31;
    int c = lane << 2;
    int s0 = g_off[w], s1 = g_off[w + 1];
    float4 z = make_float4(0.f, 0.f, 0.f, 0.f);
    if (s0 < s1) {
        float gx = 0.f, gy = 0.f, gz = 0.f, gw = 0.f;
        float d0 = 0.f, d1 = 0.f, d2 = 0.f, d3 = 0.f;
        float n0 = 0.f, n1 = 0.f, n2 = 0.f, n3 = 0.f;
#pragma unroll 2
        for (int e = s0; e < s1; e++) {
            int pk = __ldg(&g_pk[e]);
            float wn = __ldg(&g_nrm[e]);
            int s = pk >> 2, t = pk & 3;
            float4 xj = *(const float4*)(g_xw + ((size_t)s << 7) + c);
            uint4 ep = *(const uint4*)(g_erp + ((size_t)s << 9) + (t << 7) + c);
            float2 a0 = __bfloat1622float2(*(__nv_bfloat162*)&ep.x);
            float2 a1 = __bfloat1622float2(*(__nv_bfloat162*)&ep.y);
            float2 a2 = __bfloat1622float2(*(__nv_bfloat162*)&ep.z);
            float2 a3 = __bfloat1622float2(*(__nv_bfloat162*)&ep.w);
            d0 += a0.x; n0 += a0.y;
            d1 += a1.x; n1 += a1.y;
            d2 += a2.x; n2 += a2.y;
            d3 += a3.x; n3 += a3.y;
            gx += xj.x * wn; gy += xj.y * wn; gz += xj.z * wn; gw += xj.w * wn;
        }
        z.x = gx + 0.1f * fmaxf(n0 / d0, 0.f);
        z.y = gy + 0.1f * fmaxf(n1 / d1, 0.f);
        z.z = gz + 0.1f * fmaxf(n2 / d2, 0.f);
        z.w = gw + 0.1f * fmaxf(n3 / d3, 0.f);
    }
    __nv_bfloat16 h0 = __float2bfloat16_rn(z.x), h1 = __float2bfloat16_rn(z.y);
    __nv_bfloat16 h2 = __float2bfloat16_rn(z.z), h3 = __float2bfloat16_rn(z.w);
    __nv_bfloat16 l0 = __float2bfloat16_rn(z.x - __bfloat162float(h0));
    __nv_bfloat16 l1 = __float2bfloat16_rn(z.y - __bfloat162float(h1));
    __nv_bfloat16 l2 = __float2bfloat16_rn(z.z - __bfloat162float(h2));
    __nv_bfloat16 l3 = __float2bfloat16_rn(z.w - __bfloat162float(h3));
    __nv_bfloat162 ph0 = __halves2bfloat162(h0, h1), ph1 = __halves2bfloat162(h2, h3);
    __nv_bfloat162 pl0 = __halves2bfloat162(l0, l1), pl1 = __halves2bfloat162(l2, l3);
    size_t o = ((size_t)w << 7) + c;
    *(uint2*)(g_zh + o) = make_uint2(*(unsigned*)&ph0, *(unsigned*)&ph1);
    *(uint2*)(g_zl + o) = make_uint2(*(unsigned*)&pl0, *(unsigned*)&pl1);
}

// ---------------- host launcher ----------------
static void* sym_addr(const void* sym) {
    void* p = nullptr;
    cudaGetSymbolAddress(&p, sym);
    return p;
}

extern "C" void kernel_launch(void* const* d_in, const int* in_sizes, int n_in,
                              void* d_out, int out_size) {
    int ix, iei, iidx, iet, ipw, ipb, ibg, ibb, iww, iwb, iwr, iow, iob;
    if (in_sizes[1] > 1000000) {
        ix = 0; iei = 1; iidx = 2; iet = 3; ipw = 5; ipb = 6; ibg = 7; ibb = 8;
        iww = 9; iwb = 10; iwr = 11; iow = 12; iob = 13;
    } else {
        ix = 0; ipw = 2; ipb = 3; ibg = 4; ibb = 5; iww = 6; iwb = 7;
        iwr = 8; iow = 9; iob = 10; iei = 11; iet = 12; iidx = 13;
    }

    const float* x   = (const float*)d_in[ix];
    const int*   ei  = (const int*)d_in[iei];
    const int*   et  = (const int*)d_in[iet];
    const int*   idx = (const int*)d_in[iidx];
    const float* pw  = (const float*)d_in[ipw];
    const float* pb  = (const float*)d_in[ipb];
    const float* bg  = (const float*)d_in[ibg];
    const float* bb  = (const float*)d_in[ibb];
    const float* ww  = (const float*)d_in[iww];
    const float* wb  = (const float*)d_in[iwb];
    const float* wr  = (const float*)d_in[iwr];
    const float* ow  = (const float*)d_in[iow];
    const float* ob  = (const float*)d_in[iob];

    int E  = in_sizes[iei] / 2;
    int NI = out_size / 128;

    float* hbuf  = (float*)sym_addr(g_h);
    __nv_bfloat16* hh  = (__nv_bfloat16*)sym_addr(g_hh);
    __nv_bfloat16* hl  = (__nv_bfloat16*)sym_addr(g_hl);
    __nv_bfloat16* xsh = (__nv_bfloat16*)sym_addr(g_xsh);
    __nv_bfloat16* xsl = (__nv_bfloat16*)sym_addr(g_xsl);
    __nv_bfloat16* zh  = (__nv_bfloat16*)sym_addr(g_zh);
    __nv_bfloat16* zl  = (__nv_bfloat16*)sym_addr(g_zl);
    float* bc0 = (float*)sym_addr(g_bc0);
    float* b01 = (float*)sym_addr(g_b01);
    __nv_bfloat16* wc0h = (__nv_bfloat16*)sym_addr(g_wc0h);
    __nv_bfloat16* wc0l = (__nv_bfloat16*)sym_addr(g_wc0l);
    __nv_bfloat16* w01h = (__nv_bfloat16*)sym_addr(g_w01h);
    __nv_bfloat16* w01l = (__nv_bfloat16*)sym_addr(g_w01l);
    __nv_bfloat16* pwh = (__nv_bfloat16*)sym_addr(g_pwh);
    __nv_bfloat16* pwl = (__nv_bfloat16*)sym_addr(g_pwl);
    __nv_bfloat16* owh = (__nv_bfloat16*)sym_addr(g_owh);
    __nv_bfloat16* owl = (__nv_bfloat16*)sym_addr(g_owl);

    // second stream + events for parallel CSR branch (created/destroyed each call;
    // host-side only, deterministic, capture-legal)
    cudaStream_t s2;
    cudaStreamCreateWithFlags(&s2, cudaStreamNonBlocking);
    cudaEvent_t evFork, evPrep1, evJoin;
    cudaEventCreateWithFlags(&evFork, cudaEventDisableTiming);
    cudaEventCreateWithFlags(&evPrep1, cudaEventDisableTiming);
    cudaEventCreateWithFlags(&evJoin, cudaEventDisableTiming);

    // fork: CSR chain on s2
    cudaEventRecord(evFork, 0);
    cudaStreamWaitEvent(s2, evFork, 0);
    zero_kernel<<<(NN + 255) / 256, 256, 0, s2>>>();
    hist_kernel<<<(E + 255) / 256, 256, 0, s2>>>(ei, E);
    scan1_kernel<<<NB, 1024, 0, s2>>>();
    scan3_kernel<<<NB, 1024, 0, s2>>>(E);
    scatter_kernel<<<(E + 255) / 256, 256, 0, s2>>>(ei, et, E);

    // main stream: prep1 (x split + weight prep)
    int prep1_total = XS + 16384 + 16384 + 163840 + 1280;
    prep1_kernel<<<(prep1_total + 255) / 256, 256>>>(x, pw, ow, ww, wr, wb);
    cudaEventRecord(evPrep1, 0);

    // s2: prep2 after CSR chain + prep1 (needs g_wc1)
    cudaStreamWaitEvent(s2, evPrep1, 0);
    prep2_kernel<<<(81920 + 640 + 255) / 256, 256, 0, s2>>>(ow, ob);
    cudaEventRecord(evJoin, s2);

    int mtiles = (NN + 127) / 128;

    // main: projection (+ fused column stats) + BN/relu/split + layer0 GEMM
    gemm_bf16<0><<<dim3(1, mtiles), 256>>>(xsh, xsl, pwh, pwl, pb, hbuf, NN, 128, 128, nullptr);
    bnrelu_kernel<<<(NN * 128 + 255) / 256, 256>>>(bg, bb);
    gemm_bf16<1><<<dim3(5, mtiles), 256>>>(hh, hl, wc0h, wc0l, bc0, nullptr, NN, 640, 0, nullptr);

    // join: edge stage needs CSR (s2) + layer0 GEMM (main); layer1 GEMM needs prep2
    cudaStreamWaitEvent(0, evJoin, 0);
    edge_kernel<<<(NN * 32 + 255) / 256, 256>>>();

    // layer 1 (fused layer0-out)
    gemm_bf16<1><<<dim3(5, mtiles), 256>>>(zh, zl, w01h, w01l, b01, nullptr, NN, 640, 0, nullptr);
    edge_kernel<<<(NN * 32 + 255) / 256, 256>>>();

    // final: out = gelu(z1[idx] @ out_w1 + ob1)
    gemm_bf16<2><<<dim3(1, (NI + 127) / 128), 256>>>(zh, zl, owh, owl, ob + 128, (float*)d_out,
                                                     NI, 128, 128, idx);

    cudaEventDestroy(evFork);
    cudaEventDestroy(evPrep1);
    cudaEventDestroy(evJoin);
    cudaStreamDestroy(s2);
}